// round 2
// baseline (speedup 1.0000x reference)
#include <cuda_runtime.h>

#define B_    4
#define N_    4096
#define K_    16
#define CIN   128
#define H     256
#define COUT  128
#define NODES (B_*N_)   // 16384

// Scratch (device globals: allocation-free per harness rules)
__device__ float g_A [NODES*H];   // feats @ W1[:128]   (self half)
__device__ float g_Bm[NODES*H];   // feats @ W1[128:]   (neighbor half)
__device__ float g_S [NODES*H];   // sum_k mask*h2

// ---------------------------------------------------------------------------
// Kernel 1:  [16384 x 128] @ [128 x 512]  ->  g_A | g_Bm
// Tile: BM=128, BN=128, BK=32. 256 threads, 8x8 accum per thread.
// blockIdx.y: 0,1 -> A halves; 2,3 -> B halves.
// ---------------------------------------------------------------------------
__global__ __launch_bounds__(256, 2)
void k1_gemm(const float* __restrict__ feats, const float* __restrict__ W1)
{
    __shared__ float sF[128*36];   // padded rows (36 floats) to spread banks
    __shared__ float sW[32*128];

    int tid = threadIdx.x;
    int tx = tid & 15, ty = tid >> 4;
    int m0 = blockIdx.x * 128;
    int by = blockIdx.y;
    const float* Wbase = W1 + ((by >> 1) ? (128*256) : 0) + (by & 1) * 128;
    float* Out = ((by >> 1) ? g_Bm : g_A) + (by & 1) * 128;

    float acc[8][8];
    #pragma unroll
    for (int i = 0; i < 8; ++i)
        #pragma unroll
        for (int j = 0; j < 8; ++j) acc[i][j] = 0.f;

    for (int kc = 0; kc < 4; ++kc) {
        #pragma unroll
        for (int it = 0; it < 4; ++it) {           // feats tile [128][32]
            int t4 = tid + 256*it;
            int r = t4 >> 3, c4 = t4 & 7;
            float4 v = *(const float4*)(feats + (m0 + r)*CIN + kc*32 + c4*4);
            *(float4*)(sF + r*36 + c4*4) = v;
        }
        #pragma unroll
        for (int it = 0; it < 4; ++it) {           // W tile [32][128]
            int t4 = tid + 256*it;
            int r = t4 >> 5, j4 = t4 & 31;
            float4 v = *(const float4*)(Wbase + (kc*32 + r)*256 + j4*4);
            *(float4*)(sW + r*128 + j4*4) = v;
        }
        __syncthreads();
        #pragma unroll 8
        for (int kk = 0; kk < 32; ++kk) {
            float a[8], w[8];
            #pragma unroll
            for (int i = 0; i < 8; ++i) a[i] = sF[(ty + 16*i)*36 + kk];
            #pragma unroll
            for (int j = 0; j < 8; ++j) w[j] = sW[kk*128 + tx + 16*j];
            #pragma unroll
            for (int i = 0; i < 8; ++i)
                #pragma unroll
                for (int j = 0; j < 8; ++j) acc[i][j] += a[i]*w[j];
        }
        __syncthreads();
    }

    #pragma unroll
    for (int i = 0; i < 8; ++i) {
        int m = m0 + ty + 16*i;
        #pragma unroll
        for (int j = 0; j < 8; ++j)
            Out[m*H + tx + 16*j] = acc[i][j];
    }
}

// ---------------------------------------------------------------------------
// Kernel 2: fused edge MLP layer 2 + masked K-reduction.
// CTA = 8 nodes x 16 neighbors = 128 edges.
//   h1[e] = relu(A[node] + Bm[gather] + b1)           (smem, 128x256 fp32)
//   h2[e] = relu(h1 @ W2 + b2)                        (tiled GEMM, 8x8/thread)
//   S[node] = sum_k valid * h2                        (in-smem reduce)
// 512 threads: tx = lane (outputs), ty = warp (edges e = ty + 16*i).
// ---------------------------------------------------------------------------
__global__ __launch_bounds__(512, 1)
void k2_edge(const int* __restrict__ n_idxs, const int* __restrict__ nvalid,
             const float* __restrict__ W2, const float* __restrict__ b1,
             const float* __restrict__ b2)
{
    extern __shared__ float smem[];
    float* sh1 = smem;                 // 128*256 floats (also reused for partials)
    float* sW  = smem + 128*256;       // 64*256 floats
    float* sb  = sW + 64*256;          // 512 floats (b1|b2)
    int*   s_idx = (int*)(sb + 512);   // 128
    int*   s_val = s_idx + 128;        // 128

    int tid = threadIdx.x;
    int tx = tid & 31, ty = tid >> 5;
    int node0 = blockIdx.x * 8;

    if (tid < 128) {
        s_idx[tid] = n_idxs[node0*K_ + tid];
        s_val[tid] = nvalid[node0*K_ + tid];
    }
    if (tid < 256) sb[tid] = b1[tid];
    else           sb[tid] = b2[tid - 256];
    __syncthreads();

    // Build h1 tile: 8192 float4, 16 per thread
    #pragma unroll
    for (int it = 0; it < 16; ++it) {
        int t4 = tid + 512*it;
        int e = t4 >> 6, c4 = t4 & 63;
        int g  = node0 + (e >> 4);
        int gn = (g >> 12) * N_ + s_idx[e];
        float4 a  = *(const float4*)(g_A  + g *H + c4*4);
        float4 b  = *(const float4*)(g_Bm + gn*H + c4*4);
        float4 bb = *(const float4*)(sb + c4*4);
        float4 h;
        h.x = fmaxf(a.x + b.x + bb.x, 0.f);
        h.y = fmaxf(a.y + b.y + bb.y, 0.f);
        h.z = fmaxf(a.z + b.z + bb.z, 0.f);
        h.w = fmaxf(a.w + b.w + bb.w, 0.f);
        *(float4*)(sh1 + e*H + c4*4) = h;
    }
    __syncthreads();

    float acc[8][8];
    #pragma unroll
    for (int i = 0; i < 8; ++i)
        #pragma unroll
        for (int j = 0; j < 8; ++j) acc[i][j] = 0.f;

    for (int kc = 0; kc < 4; ++kc) {
        #pragma unroll
        for (int it = 0; it < 8; ++it) {           // W2 chunk [64][256]
            int t4 = tid + 512*it;
            int r = t4 >> 6, c4 = t4 & 63;
            *(float4*)(sW + r*256 + c4*4) =
                *(const float4*)(W2 + (kc*64 + r)*256 + c4*4);
        }
        __syncthreads();
        const float* h1k = sh1 + kc*64;
        #pragma unroll 8
        for (int kk = 0; kk < 64; ++kk) {
            float a[8], w[8];
            #pragma unroll
            for (int i = 0; i < 8; ++i) a[i] = h1k[(ty + 16*i)*H + kk];  // warp broadcast
            #pragma unroll
            for (int j = 0; j < 8; ++j) w[j] = sW[kk*256 + tx + 32*j];   // conflict-free
            #pragma unroll
            for (int i = 0; i < 8; ++i)
                #pragma unroll
                for (int j = 0; j < 8; ++j) acc[i][j] += a[i]*w[j];
        }
        __syncthreads();
    }

    // bias + relu + mask -> partials in sh1 laid out [ty][node i][o]
    #pragma unroll
    for (int i = 0; i < 8; ++i) {
        float m = s_val[i*16 + ty] ? 1.f : 0.f;     // edge e = i*16 + ty
        #pragma unroll
        for (int j = 0; j < 8; ++j) {
            int o = tx + 32*j;
            sh1[ty*2048 + i*256 + o] = fmaxf(acc[i][j] + sb[256 + o], 0.f) * m;
        }
    }
    __syncthreads();

    // reduce over 16 warps (k dim) -> g_S
    #pragma unroll
    for (int r = 0; r < 4; ++r) {
        int oi = tid + 512*r;                        // i*256 + o, 0..2047
        float s = 0.f;
        #pragma unroll
        for (int w = 0; w < 16; ++w) s += sh1[w*2048 + oi];
        g_S[node0*H + oi] = s;
    }
}

// ---------------------------------------------------------------------------
// Kernel 3:  out = g_S[16384x256] @ W3[256x128] + b3 * valid_count
// ---------------------------------------------------------------------------
__global__ __launch_bounds__(256, 2)
void k3_gemm(const int* __restrict__ nvalid, const float* __restrict__ W3,
             const float* __restrict__ b3, float* __restrict__ out)
{
    __shared__ float sS[128*36];
    __shared__ float sW[32*128];
    __shared__ float sb3[128];
    __shared__ float s_cnt[128];

    int tid = threadIdx.x;
    int tx = tid & 15, ty = tid >> 4;
    int m0 = blockIdx.x * 128;

    if (tid < 128) {
        sb3[tid] = b3[tid];
        int c = 0;
        #pragma unroll
        for (int k = 0; k < K_; ++k) c += nvalid[(m0 + tid)*K_ + k];
        s_cnt[tid] = (float)c;
    }

    float acc[8][8];
    #pragma unroll
    for (int i = 0; i < 8; ++i)
        #pragma unroll
        for (int j = 0; j < 8; ++j) acc[i][j] = 0.f;

    for (int kc = 0; kc < 8; ++kc) {
        #pragma unroll
        for (int it = 0; it < 4; ++it) {           // S tile [128][32]
            int t4 = tid + 256*it;
            int r = t4 >> 3, c4 = t4 & 7;
            *(float4*)(sS + r*36 + c4*4) =
                *(const float4*)(g_S + (m0 + r)*H + kc*32 + c4*4);
        }
        #pragma unroll
        for (int it = 0; it < 4; ++it) {           // W3 tile [32][128]
            int t4 = tid + 256*it;
            int r = t4 >> 5, j4 = t4 & 31;
            *(float4*)(sW + r*128 + j4*4) =
                *(const float4*)(W3 + (kc*32 + r)*COUT + j4*4);
        }
        __syncthreads();
        #pragma unroll 8
        for (int kk = 0; kk < 32; ++kk) {
            float a[8], w[8];
            #pragma unroll
            for (int i = 0; i < 8; ++i) a[i] = sS[(ty + 16*i)*36 + kk];
            #pragma unroll
            for (int j = 0; j < 8; ++j) w[j] = sW[kk*128 + tx + 16*j];
            #pragma unroll
            for (int i = 0; i < 8; ++i)
                #pragma unroll
                for (int j = 0; j < 8; ++j) acc[i][j] += a[i]*w[j];
        }
        __syncthreads();
    }

    #pragma unroll
    for (int i = 0; i < 8; ++i) {
        int m = ty + 16*i;
        #pragma unroll
        for (int j = 0; j < 8; ++j) {
            int o = tx + 16*j;
            out[(m0 + m)*COUT + o] = acc[i][j] + sb3[o]*s_cnt[m];
        }
    }
}

// ---------------------------------------------------------------------------
extern "C" void kernel_launch(void* const* d_in, const int* in_sizes, int n_in,
                              void* d_out, int out_size)
{
    // metadata order: keys, points, feats, n_idxs, neighbor_valid,
    //                 W1, b1, W2, b2, W3, b3   (keys/points unused)
    const float* feats  = (const float*)d_in[2];
    const int*   n_idxs = (const int*)  d_in[3];
    const int*   nvalid = (const int*)  d_in[4];
    const float* W1     = (const float*)d_in[5];
    const float* b1     = (const float*)d_in[6];
    const float* W2     = (const float*)d_in[7];
    const float* b2     = (const float*)d_in[8];
    const float* W3     = (const float*)d_in[9];
    const float* b3     = (const float*)d_in[10];
    float* out = (float*)d_out;

    const int smem2 = (128*256 + 64*256 + 512)*4 + 256*4;   // 199680 B
    cudaFuncSetAttribute(k2_edge, cudaFuncAttributeMaxDynamicSharedMemorySize, smem2);

    k1_gemm<<<dim3(NODES/128, 4), 256>>>(feats, W1);
    k2_edge<<<NODES/8, 512, smem2>>>(n_idxs, nvalid, W2, b1, b2);
    k3_gemm<<<NODES/128, 256>>>(nvalid, W3, b3, out);
}

// round 4
// speedup vs baseline: 2.0545x; 2.0545x over previous
#include <cuda_runtime.h>
#include <cuda_bf16.h>
#include <cstdint>

#define B_    4
#define N_    4096
#define K_    16
#define H     256
#define COUT  128
#define NODES (B_*N_)

__device__ float g_A [NODES*H];   // feats @ W1[:,:128] + b1 (self half, bias folded)
__device__ float g_Bm[NODES*H];   // feats @ W1[:,128:]  (neighbor half)
__device__ float g_S [NODES*H];   // sum_k mask*h2
// W2 split/packed: [chunk c:8][hi=0,lo=1][n:256][k:40 padded] bf16
__device__ __align__(16) uint16_t g_W2p[8*2*256*40];

// ---------------- helpers ----------------
__device__ __forceinline__ uint32_t smem_u32(const void* p) {
    uint32_t a;
    asm("{ .reg .u64 t; cvta.to.shared.u64 t, %1; cvt.u32.u64 %0, t; }" : "=r"(a) : "l"(p));
    return a;
}
__device__ __forceinline__ void mma_bf16(float* d, const uint32_t* a, const uint32_t* b) {
    asm volatile("mma.sync.aligned.m16n8k16.row.col.f32.bf16.bf16.f32 "
        "{%0,%1,%2,%3}, {%4,%5,%6,%7}, {%8,%9}, {%0,%1,%2,%3};"
        : "+f"(d[0]), "+f"(d[1]), "+f"(d[2]), "+f"(d[3])
        : "r"(a[0]), "r"(a[1]), "r"(a[2]), "r"(a[3]), "r"(b[0]), "r"(b[1]));
}
__device__ __forceinline__ void cp16(uint32_t sdst, const void* gsrc) {
    asm volatile("cp.async.cg.shared.global [%0], [%1], 16;" :: "r"(sdst), "l"(gsrc));
}
__device__ __forceinline__ void split2(float x, float y, uint32_t& hi, uint32_t& lo) {
    __nv_bfloat16 hx = __float2bfloat16(x), hy = __float2bfloat16(y);
    __nv_bfloat16 lx = __float2bfloat16(x - __bfloat162float(hx));
    __nv_bfloat16 ly = __float2bfloat16(y - __bfloat162float(hy));
    __nv_bfloat162 hp(hx, hy), lp(lx, ly);
    hi = *reinterpret_cast<uint32_t*>(&hp);
    lo = *reinterpret_cast<uint32_t*>(&lp);
}

// smem byte offsets for k2 (total 219136)
#define OFF_H1HI 0
#define OFF_H1LO 67584
#define OFF_W    135168     // 2 stages x (hi 20480 + lo 20480)
#define OFF_B2   217088
#define OFF_SIDX 218112
#define OFF_SVAL 218624
#define SMEM2    219136

// ---------------------------------------------------------------------------
// k0: split W2 into bf16 hi/lo, pack n-major padded chunks
// ---------------------------------------------------------------------------
__global__ void k0_prep(const float* __restrict__ W2)
{
    int i = blockIdx.x * 256 + threadIdx.x;   // 8*2*256*40 = 163840
    if (i >= 163840) return;
    int kl = i % 40;
    int n  = (i / 40) % 256;
    int hl = (i / (40*256)) % 2;
    int c  = i / (40*256*2);
    uint16_t v = 0;
    if (kl < 32) {
        float w = W2[(c*32 + kl)*256 + n];
        __nv_bfloat16 hi = __float2bfloat16(w);
        if (hl == 0) v = *reinterpret_cast<uint16_t*>(&hi);
        else {
            __nv_bfloat16 lo = __float2bfloat16(w - __bfloat162float(hi));
            v = *reinterpret_cast<uint16_t*>(&lo);
        }
    }
    g_W2p[i] = v;
}

// ---------------------------------------------------------------------------
// k1: [16384x128] @ [128x512] -> g_A (b1 folded) | g_Bm
// ---------------------------------------------------------------------------
__global__ __launch_bounds__(256, 2)
void k1_gemm(const float* __restrict__ feats, const float* __restrict__ W1,
             const float* __restrict__ b1)
{
    __shared__ float sF[128*36];
    __shared__ float sW[32*128];
    int tid = threadIdx.x, tx = tid & 15, ty = tid >> 4;
    int m0 = blockIdx.x * 128, by = blockIdx.y;
    const float* Wbase = W1 + ((by >> 1) ? (128*256) : 0) + (by & 1) * 128;
    float* Out = ((by >> 1) ? g_Bm : g_A) + (by & 1) * 128;
    float acc[8][8];
    #pragma unroll
    for (int i = 0; i < 8; ++i)
        #pragma unroll
        for (int j = 0; j < 8; ++j) acc[i][j] = 0.f;
    for (int kc = 0; kc < 4; ++kc) {
        #pragma unroll
        for (int it = 0; it < 4; ++it) {
            int t4 = tid + 256*it, r = t4 >> 3, c4 = t4 & 7;
            *(float4*)(sF + r*36 + c4*4) = *(const float4*)(feats + (m0 + r)*128 + kc*32 + c4*4);
        }
        #pragma unroll
        for (int it = 0; it < 4; ++it) {
            int t4 = tid + 256*it, r = t4 >> 5, j4 = t4 & 31;
            *(float4*)(sW + r*128 + j4*4) = *(const float4*)(Wbase + (kc*32 + r)*256 + j4*4);
        }
        __syncthreads();
        #pragma unroll 8
        for (int kk = 0; kk < 32; ++kk) {
            float a[8], w[8];
            #pragma unroll
            for (int i = 0; i < 8; ++i) a[i] = sF[(ty + 16*i)*36 + kk];
            #pragma unroll
            for (int j = 0; j < 8; ++j) w[j] = sW[kk*128 + tx + 16*j];
            #pragma unroll
            for (int i = 0; i < 8; ++i)
                #pragma unroll
                for (int j = 0; j < 8; ++j) acc[i][j] += a[i]*w[j];
        }
        __syncthreads();
    }
    bool isA = (by < 2);
    #pragma unroll
    for (int i = 0; i < 8; ++i) {
        int m = m0 + ty + 16*i;
        #pragma unroll
        for (int j = 0; j < 8; ++j) {
            float bias = isA ? b1[(by & 1)*128 + tx + 16*j] : 0.f;
            Out[m*H + tx + 16*j] = acc[i][j] + bias;
        }
    }
}

// ---------------------------------------------------------------------------
// k2: edge MLP layer-2 via mma.sync bf16 3-term split + masked K-reduction.
// CTA = 8 nodes x 16 edges = 128 rows, 256 outputs. 256 threads, 8 warps.
// ---------------------------------------------------------------------------
__global__ __launch_bounds__(256, 1)
void k2_edge(const int* __restrict__ n_idxs, const int* __restrict__ nvalid,
             const float* __restrict__ b2)
{
    extern __shared__ char smem[];
    uint16_t* sh1hi = (uint16_t*)(smem + OFF_H1HI);   // [128][264]
    uint16_t* sh1lo = (uint16_t*)(smem + OFF_H1LO);
    float*    sb2   = (float*)(smem + OFF_B2);
    int*      sidx  = (int*)(smem + OFF_SIDX);
    float*    sval  = (float*)(smem + OFF_SVAL);
    uint32_t  swbase = smem_u32(smem) + OFF_W;

    int tid = threadIdx.x, lane = tid & 31, wid = tid >> 5;
    int wm = wid >> 2, wn = wid & 3;
    int node0 = blockIdx.x * 8;

    // prologue: kick cp.async for W chunks 0 and 1 (40960B each, 10x16B/thread)
    #pragma unroll
    for (int s = 0; s < 2; ++s) {
        const char* src = (const char*)g_W2p + s*40960 + tid*16;
        uint32_t dst = swbase + s*40960 + tid*16;
        #pragma unroll
        for (int it = 0; it < 10; ++it)
            cp16(dst + it*4096, src + it*4096);
        asm volatile("cp.async.commit_group;" ::: "memory");
    }

    // stage small stuff
    if (tid < 128) {
        sidx[tid] = n_idxs[node0*K_ + tid];
        sval[tid] = nvalid[node0*K_ + tid] ? 1.f : 0.f;
    }
    sb2[tid] = b2[tid];
    __syncthreads();   // sidx visible for build

    // build h1 hi/lo: thread t -> row t/2, col half (t&1)*128
    {
        int e = tid >> 1, cb = (tid & 1) * 128;
        int node = node0 + (e >> 4);
        int gn = (node >> 12) * N_ + sidx[e];
        const float* ar = g_A  + (size_t)node * H + cb;
        const float* br = g_Bm + (size_t)gn   * H + cb;
        uint16_t* ph = sh1hi + e*264 + cb;
        uint16_t* pl = sh1lo + e*264 + cb;
        #pragma unroll
        for (int j = 0; j < 32; ++j) {
            float4 av = *(const float4*)(ar + 4*j);
            float4 bv = *(const float4*)(br + 4*j);
            float h0 = fmaxf(av.x + bv.x, 0.f), h1 = fmaxf(av.y + bv.y, 0.f);
            float h2 = fmaxf(av.z + bv.z, 0.f), h3 = fmaxf(av.w + bv.w, 0.f);
            uint32_t hi01, lo01, hi23, lo23;
            split2(h0, h1, hi01, lo01);
            split2(h2, h3, hi23, lo23);
            *(uint32_t*)(ph + 4*j)     = hi01;
            *(uint32_t*)(ph + 4*j + 2) = hi23;
            *(uint32_t*)(pl + 4*j)     = lo01;
            *(uint32_t*)(pl + 4*j + 2) = lo23;
        }
    }

    float acc[4][8][4];
    #pragma unroll
    for (int mi = 0; mi < 4; ++mi)
        #pragma unroll
        for (int ni = 0; ni < 8; ++ni)
            #pragma unroll
            for (int q = 0; q < 4; ++q) acc[mi][ni][q] = 0.f;

    int g4 = lane >> 2, l4 = lane & 3;    // frag row-group / col-group

    // 8 k-chunks of 32, double-buffered weights
    for (int c = 0; c < 8; ++c) {
        if (c == 7) asm volatile("cp.async.wait_group 0;" ::: "memory");
        else        asm volatile("cp.async.wait_group 1;" ::: "memory");
        __syncthreads();

        const uint16_t* sWh = (const uint16_t*)(smem + OFF_W + (c & 1)*40960);
        const uint16_t* sWl = sWh + 10240;

        #pragma unroll
        for (int ks = 0; ks < 2; ++ks) {
            uint32_t bh[8][2], bl[8][2];
            #pragma unroll
            for (int ni = 0; ni < 8; ++ni) {
                int n = wn*64 + ni*8 + g4;
                const uint16_t* p = sWh + n*40 + ks*16 + l4*2;
                bh[ni][0] = *(const uint32_t*)p;
                bh[ni][1] = *(const uint32_t*)(p + 8);
                const uint16_t* q = sWl + n*40 + ks*16 + l4*2;
                bl[ni][0] = *(const uint32_t*)q;
                bl[ni][1] = *(const uint32_t*)(q + 8);
            }
            int kk = c*32 + ks*16 + l4*2;
            #pragma unroll
            for (int mi = 0; mi < 4; ++mi) {
                int m = wm*64 + mi*16 + g4;
                uint32_t ah[4], al[4];
                const uint16_t* pa = sh1hi + m*264 + kk;
                ah[0] = *(const uint32_t*)pa;
                ah[1] = *(const uint32_t*)(pa + 8*264);
                ah[2] = *(const uint32_t*)(pa + 8);
                ah[3] = *(const uint32_t*)(pa + 8*264 + 8);
                const uint16_t* pb = sh1lo + m*264 + kk;
                al[0] = *(const uint32_t*)pb;
                al[1] = *(const uint32_t*)(pb + 8*264);
                al[2] = *(const uint32_t*)(pb + 8);
                al[3] = *(const uint32_t*)(pb + 8*264 + 8);
                #pragma unroll
                for (int ni = 0; ni < 8; ++ni) {
                    mma_bf16(acc[mi][ni], ah, bh[ni]);
                    mma_bf16(acc[mi][ni], al, bh[ni]);
                    mma_bf16(acc[mi][ni], ah, bl[ni]);
                }
            }
        }
        __syncthreads();
        if (c < 6) {   // refill this stage with chunk c+2
            const char* src = (const char*)g_W2p + (c + 2)*40960 + tid*16;
            uint32_t dst = swbase + (c & 1)*40960 + tid*16;
            #pragma unroll
            for (int it = 0; it < 10; ++it)
                cp16(dst + it*4096, src + it*4096);
            asm volatile("cp.async.commit_group;" ::: "memory");
        }
    }

    // epilogue: bias + relu + mask, butterfly over 16 edges, store g_S
    #pragma unroll
    for (int mi = 0; mi < 4; ++mi) {
        int node_l = wm*4 + mi;
        float m1 = sval[node_l*16 + g4];
        float m2 = sval[node_l*16 + g4 + 8];
        int node_g = node0 + node_l;
        #pragma unroll
        for (int ni = 0; ni < 8; ++ni) {
            int n0 = wn*64 + ni*8 + l4*2;
            float s0 = fmaxf(acc[mi][ni][0] + sb2[n0],     0.f)*m1
                     + fmaxf(acc[mi][ni][2] + sb2[n0],     0.f)*m2;
            float s1 = fmaxf(acc[mi][ni][1] + sb2[n0 + 1], 0.f)*m1
                     + fmaxf(acc[mi][ni][3] + sb2[n0 + 1], 0.f)*m2;
            #pragma unroll
            for (int d = 4; d < 32; d <<= 1) {
                s0 += __shfl_xor_sync(0xFFFFFFFF, s0, d);
                s1 += __shfl_xor_sync(0xFFFFFFFF, s1, d);
            }
            if (g4 == 0)
                *(float2*)(g_S + (size_t)node_g*H + n0) = make_float2(s0, s1);
        }
    }
}

// ---------------------------------------------------------------------------
// k3: out = g_S @ W3 + b3 * valid_count
// ---------------------------------------------------------------------------
__global__ __launch_bounds__(256, 2)
void k3_gemm(const int* __restrict__ nvalid, const float* __restrict__ W3,
             const float* __restrict__ b3, float* __restrict__ out)
{
    __shared__ float sS[128*36];
    __shared__ float sW[32*128];
    __shared__ float sb3[128];
    __shared__ float s_cnt[128];
    int tid = threadIdx.x, tx = tid & 15, ty = tid >> 4;
    int m0 = blockIdx.x * 128;
    if (tid < 128) {
        sb3[tid] = b3[tid];
        int c = 0;
        #pragma unroll
        for (int k = 0; k < K_; ++k) c += nvalid[(m0 + tid)*K_ + k];
        s_cnt[tid] = (float)c;
    }
    float acc[8][8];
    #pragma unroll
    for (int i = 0; i < 8; ++i)
        #pragma unroll
        for (int j = 0; j < 8; ++j) acc[i][j] = 0.f;
    for (int kc = 0; kc < 8; ++kc) {
        #pragma unroll
        for (int it = 0; it < 4; ++it) {
            int t4 = tid + 256*it, r = t4 >> 3, c4 = t4 & 7;
            *(float4*)(sS + r*36 + c4*4) = *(const float4*)(g_S + (m0 + r)*H + kc*32 + c4*4);
        }
        #pragma unroll
        for (int it = 0; it < 4; ++it) {
            int t4 = tid + 256*it, r = t4 >> 5, j4 = t4 & 31;
            *(float4*)(sW + r*128 + j4*4) = *(const float4*)(W3 + (kc*32 + r)*COUT + j4*4);
        }
        __syncthreads();
        #pragma unroll 8
        for (int kk = 0; kk < 32; ++kk) {
            float a[8], w[8];
            #pragma unroll
            for (int i = 0; i < 8; ++i) a[i] = sS[(ty + 16*i)*36 + kk];
            #pragma unroll
            for (int j = 0; j < 8; ++j) w[j] = sW[kk*128 + tx + 16*j];
            #pragma unroll
            for (int i = 0; i < 8; ++i)
                #pragma unroll
                for (int j = 0; j < 8; ++j) acc[i][j] += a[i]*w[j];
        }
        __syncthreads();
    }
    #pragma unroll
    for (int i = 0; i < 8; ++i) {
        int m = ty + 16*i;
        #pragma unroll
        for (int j = 0; j < 8; ++j) {
            int o = tx + 16*j;
            out[(m0 + m)*COUT + o] = acc[i][j] + sb3[o]*s_cnt[m];
        }
    }
}

// ---------------------------------------------------------------------------
extern "C" void kernel_launch(void* const* d_in, const int* in_sizes, int n_in,
                              void* d_out, int out_size)
{
    const float* feats  = (const float*)d_in[2];
    const int*   n_idxs = (const int*)  d_in[3];
    const int*   nvalid = (const int*)  d_in[4];
    const float* W1     = (const float*)d_in[5];
    const float* b1     = (const float*)d_in[6];
    const float* W2     = (const float*)d_in[7];
    const float* b2     = (const float*)d_in[8];
    const float* W3     = (const float*)d_in[9];
    const float* b3     = (const float*)d_in[10];
    float* out = (float*)d_out;

    cudaFuncSetAttribute(k2_edge, cudaFuncAttributeMaxDynamicSharedMemorySize, SMEM2);

    k0_prep<<<640, 256>>>(W2);
    k1_gemm<<<dim3(NODES/128, 4), 256>>>(feats, W1, b1);
    k2_edge<<<NODES/8, 256, SMEM2>>>(n_idxs, nvalid, b2);
    k3_gemm<<<NODES/128, 256>>>(nvalid, W3, b3, out);
}

// round 5
// speedup vs baseline: 2.0579x; 1.0016x over previous
#include <cuda_runtime.h>
#include <cuda_bf16.h>
#include <cstdint>

#define B_    4
#define N_    4096
#define K_    16
#define H     256
#define COUT  128
#define NODES (B_*N_)

__device__ float g_A [NODES*H];   // feats @ W1[:,:128] + b1 (self half, bias folded)
__device__ float g_Bm[NODES*H];   // feats @ W1[:,128:]  (neighbor half)
__device__ float g_S [NODES*H];   // sum_k mask*h2
// W2 split/packed: [chunk c:8][hi=0,lo=1][n:256][k:40 padded] bf16
__device__ __align__(16) uint16_t g_W2p[8*2*256*40];

// ---------------- helpers ----------------
__device__ __forceinline__ uint32_t smem_u32(const void* p) {
    uint32_t a;
    asm("{ .reg .u64 t; cvta.to.shared.u64 t, %1; cvt.u32.u64 %0, t; }" : "=r"(a) : "l"(p));
    return a;
}
__device__ __forceinline__ void mma_bf16(float* d, const uint32_t* a, const uint32_t* b) {
    asm volatile("mma.sync.aligned.m16n8k16.row.col.f32.bf16.bf16.f32 "
        "{%0,%1,%2,%3}, {%4,%5,%6,%7}, {%8,%9}, {%0,%1,%2,%3};"
        : "+f"(d[0]), "+f"(d[1]), "+f"(d[2]), "+f"(d[3])
        : "r"(a[0]), "r"(a[1]), "r"(a[2]), "r"(a[3]), "r"(b[0]), "r"(b[1]));
}
__device__ __forceinline__ void cp16(uint32_t sdst, const void* gsrc) {
    asm volatile("cp.async.cg.shared.global [%0], [%1], 16;" :: "r"(sdst), "l"(gsrc));
}
__device__ __forceinline__ void split2(float x, float y, uint32_t& hi, uint32_t& lo) {
    __nv_bfloat16 hx = __float2bfloat16(x), hy = __float2bfloat16(y);
    __nv_bfloat16 lx = __float2bfloat16(x - __bfloat162float(hx));
    __nv_bfloat16 ly = __float2bfloat16(y - __bfloat162float(hy));
    __nv_bfloat162 hp(hx, hy), lp(lx, ly);
    hi = *reinterpret_cast<uint32_t*>(&hp);
    lo = *reinterpret_cast<uint32_t*>(&lp);
}

// smem byte offsets for k2 (total 219136)
#define OFF_H1HI 0
#define OFF_H1LO 67584
#define OFF_W    135168     // 2 stages x (hi 20480 + lo 20480)
#define OFF_B2   217088
#define OFF_SIDX 218112
#define OFF_SVAL 218624
#define SMEM2    219136

// ---------------------------------------------------------------------------
// k0: split W2 into bf16 hi/lo, pack n-major padded chunks
// ---------------------------------------------------------------------------
__global__ void k0_prep(const float* __restrict__ W2)
{
    int i = blockIdx.x * 256 + threadIdx.x;   // 8*2*256*40 = 163840
    if (i >= 163840) return;
    int kl = i % 40;
    int n  = (i / 40) % 256;
    int hl = (i / (40*256)) % 2;
    int c  = i / (40*256*2);
    uint16_t v = 0;
    if (kl < 32) {
        float w = W2[(c*32 + kl)*256 + n];
        __nv_bfloat16 hi = __float2bfloat16(w);
        if (hl == 0) v = *reinterpret_cast<uint16_t*>(&hi);
        else {
            __nv_bfloat16 lo = __float2bfloat16(w - __bfloat162float(hi));
            v = *reinterpret_cast<uint16_t*>(&lo);
        }
    }
    g_W2p[i] = v;
}

// ---------------------------------------------------------------------------
// k1: [16384x128] @ [128x512] -> g_A (b1 folded) | g_Bm
// ---------------------------------------------------------------------------
__global__ __launch_bounds__(256, 2)
void k1_gemm(const float* __restrict__ feats, const float* __restrict__ W1,
             const float* __restrict__ b1)
{
    __shared__ float sF[128*36];
    __shared__ float sW[32*128];
    int tid = threadIdx.x, tx = tid & 15, ty = tid >> 4;
    int m0 = blockIdx.x * 128, by = blockIdx.y;
    const float* Wbase = W1 + ((by >> 1) ? (128*256) : 0) + (by & 1) * 128;
    float* Out = ((by >> 1) ? g_Bm : g_A) + (by & 1) * 128;
    float acc[8][8];
    #pragma unroll
    for (int i = 0; i < 8; ++i)
        #pragma unroll
        for (int j = 0; j < 8; ++j) acc[i][j] = 0.f;
    for (int kc = 0; kc < 4; ++kc) {
        #pragma unroll
        for (int it = 0; it < 4; ++it) {
            int t4 = tid + 256*it, r = t4 >> 3, c4 = t4 & 7;
            *(float4*)(sF + r*36 + c4*4) = *(const float4*)(feats + (m0 + r)*128 + kc*32 + c4*4);
        }
        #pragma unroll
        for (int it = 0; it < 4; ++it) {
            int t4 = tid + 256*it, r = t4 >> 5, j4 = t4 & 31;
            *(float4*)(sW + r*128 + j4*4) = *(const float4*)(Wbase + (kc*32 + r)*256 + j4*4);
        }
        __syncthreads();
        #pragma unroll 8
        for (int kk = 0; kk < 32; ++kk) {
            float a[8], w[8];
            #pragma unroll
            for (int i = 0; i < 8; ++i) a[i] = sF[(ty + 16*i)*36 + kk];
            #pragma unroll
            for (int j = 0; j < 8; ++j) w[j] = sW[kk*128 + tx + 16*j];
            #pragma unroll
            for (int i = 0; i < 8; ++i)
                #pragma unroll
                for (int j = 0; j < 8; ++j) acc[i][j] += a[i]*w[j];
        }
        __syncthreads();
    }
    bool isA = (by < 2);
    #pragma unroll
    for (int i = 0; i < 8; ++i) {
        int m = m0 + ty + 16*i;
        #pragma unroll
        for (int j = 0; j < 8; ++j) {
            float bias = isA ? b1[(by & 1)*128 + tx + 16*j] : 0.f;
            Out[m*H + tx + 16*j] = acc[i][j] + bias;
        }
    }
}

// ---------------------------------------------------------------------------
// k2: edge MLP layer-2 via mma.sync bf16 3-term split + masked K-reduction.
// CTA = 8 nodes x 16 edges = 128 rows, 256 outputs. 256 threads, 8 warps.
// Term-major mma ordering: 32 independent accumulators between acc reuses.
// ---------------------------------------------------------------------------
__global__ __launch_bounds__(256, 1)
void k2_edge(const int* __restrict__ n_idxs, const int* __restrict__ nvalid,
             const float* __restrict__ b2)
{
    extern __shared__ char smem[];
    uint16_t* sh1hi = (uint16_t*)(smem + OFF_H1HI);   // [128][264]
    uint16_t* sh1lo = (uint16_t*)(smem + OFF_H1LO);
    float*    sb2   = (float*)(smem + OFF_B2);
    int*      sidx  = (int*)(smem + OFF_SIDX);
    float*    sval  = (float*)(smem + OFF_SVAL);
    uint32_t  swbase = smem_u32(smem) + OFF_W;

    int tid = threadIdx.x, lane = tid & 31, wid = tid >> 5;
    int wm = wid >> 2, wn = wid & 3;
    int node0 = blockIdx.x * 8;

    // prologue: kick cp.async for W chunks 0 and 1 (40960B each, 10x16B/thread)
    #pragma unroll
    for (int s = 0; s < 2; ++s) {
        const char* src = (const char*)g_W2p + s*40960 + tid*16;
        uint32_t dst = swbase + s*40960 + tid*16;
        #pragma unroll
        for (int it = 0; it < 10; ++it)
            cp16(dst + it*4096, src + it*4096);
        asm volatile("cp.async.commit_group;" ::: "memory");
    }

    // stage small stuff
    if (tid < 128) {
        sidx[tid] = n_idxs[node0*K_ + tid];
        sval[tid] = nvalid[node0*K_ + tid] ? 1.f : 0.f;
    }
    sb2[tid] = b2[tid];
    __syncthreads();   // sidx visible for build

    // build h1 hi/lo: thread t -> row t/2, col half (t&1)*128
    {
        int e = tid >> 1, cb = (tid & 1) * 128;
        int node = node0 + (e >> 4);
        int gn = (node >> 12) * N_ + sidx[e];
        const float* ar = g_A  + (size_t)node * H + cb;
        const float* br = g_Bm + (size_t)gn   * H + cb;
        uint16_t* ph = sh1hi + e*264 + cb;
        uint16_t* pl = sh1lo + e*264 + cb;
        #pragma unroll
        for (int j = 0; j < 32; ++j) {
            float4 av = *(const float4*)(ar + 4*j);
            float4 bv = *(const float4*)(br + 4*j);
            float h0 = fmaxf(av.x + bv.x, 0.f), h1 = fmaxf(av.y + bv.y, 0.f);
            float h2 = fmaxf(av.z + bv.z, 0.f), h3 = fmaxf(av.w + bv.w, 0.f);
            uint32_t hi01, lo01, hi23, lo23;
            split2(h0, h1, hi01, lo01);
            split2(h2, h3, hi23, lo23);
            *(uint32_t*)(ph + 4*j)     = hi01;
            *(uint32_t*)(ph + 4*j + 2) = hi23;
            *(uint32_t*)(pl + 4*j)     = lo01;
            *(uint32_t*)(pl + 4*j + 2) = lo23;
        }
    }

    float acc[4][8][4];
    #pragma unroll
    for (int mi = 0; mi < 4; ++mi)
        #pragma unroll
        for (int ni = 0; ni < 8; ++ni)
            #pragma unroll
            for (int q = 0; q < 4; ++q) acc[mi][ni][q] = 0.f;

    int g4 = lane >> 2, l4 = lane & 3;    // frag row-group / col-group

    // 8 k-chunks of 32, double-buffered weights
    for (int c = 0; c < 8; ++c) {
        if (c == 7) asm volatile("cp.async.wait_group 0;" ::: "memory");
        else        asm volatile("cp.async.wait_group 1;" ::: "memory");
        __syncthreads();

        const uint16_t* sWh = (const uint16_t*)(smem + OFF_W + (c & 1)*40960);
        const uint16_t* sWl = sWh + 10240;

        #pragma unroll
        for (int ks = 0; ks < 2; ++ks) {
            int kk = c*32 + ks*16 + l4*2;

            // --- load all A-hi fragments ---
            uint32_t ah[4][4];
            #pragma unroll
            for (int mi = 0; mi < 4; ++mi) {
                const uint16_t* pa = sh1hi + (wm*64 + mi*16 + g4)*264 + kk;
                ah[mi][0] = *(const uint32_t*)pa;
                ah[mi][1] = *(const uint32_t*)(pa + 8*264);
                ah[mi][2] = *(const uint32_t*)(pa + 8);
                ah[mi][3] = *(const uint32_t*)(pa + 8*264 + 8);
            }
            // --- load all B-hi fragments ---
            uint32_t bb[8][2];
            #pragma unroll
            for (int ni = 0; ni < 8; ++ni) {
                const uint16_t* p = sWh + (wn*64 + ni*8 + g4)*40 + ks*16 + l4*2;
                bb[ni][0] = *(const uint32_t*)p;
                bb[ni][1] = *(const uint32_t*)(p + 8);
            }

            // term 1: hi * Whi  (32 independent accs)
            #pragma unroll
            for (int mi = 0; mi < 4; ++mi)
                #pragma unroll
                for (int ni = 0; ni < 8; ++ni)
                    mma_bf16(acc[mi][ni], ah[mi], bb[ni]);

            // --- load all A-lo fragments ---
            uint32_t al[4][4];
            #pragma unroll
            for (int mi = 0; mi < 4; ++mi) {
                const uint16_t* pb = sh1lo + (wm*64 + mi*16 + g4)*264 + kk;
                al[mi][0] = *(const uint32_t*)pb;
                al[mi][1] = *(const uint32_t*)(pb + 8*264);
                al[mi][2] = *(const uint32_t*)(pb + 8);
                al[mi][3] = *(const uint32_t*)(pb + 8*264 + 8);
            }

            // term 2: lo * Whi
            #pragma unroll
            for (int mi = 0; mi < 4; ++mi)
                #pragma unroll
                for (int ni = 0; ni < 8; ++ni)
                    mma_bf16(acc[mi][ni], al[mi], bb[ni]);

            // --- overwrite B regs with B-lo fragments ---
            #pragma unroll
            for (int ni = 0; ni < 8; ++ni) {
                const uint16_t* q = sWl + (wn*64 + ni*8 + g4)*40 + ks*16 + l4*2;
                bb[ni][0] = *(const uint32_t*)q;
                bb[ni][1] = *(const uint32_t*)(q + 8);
            }

            // term 3: hi * Wlo
            #pragma unroll
            for (int mi = 0; mi < 4; ++mi)
                #pragma unroll
                for (int ni = 0; ni < 8; ++ni)
                    mma_bf16(acc[mi][ni], ah[mi], bb[ni]);
        }
        __syncthreads();
        if (c < 6) {   // refill this stage with chunk c+2
            const char* src = (const char*)g_W2p + (c + 2)*40960 + tid*16;
            uint32_t dst = swbase + (c & 1)*40960 + tid*16;
            #pragma unroll
            for (int it = 0; it < 10; ++it)
                cp16(dst + it*4096, src + it*4096);
            asm volatile("cp.async.commit_group;" ::: "memory");
        }
    }

    // epilogue: bias + relu + mask, butterfly over 16 edges, store g_S
    #pragma unroll
    for (int mi = 0; mi < 4; ++mi) {
        int node_l = wm*4 + mi;
        float m1 = sval[node_l*16 + g4];
        float m2 = sval[node_l*16 + g4 + 8];
        int node_g = node0 + node_l;
        #pragma unroll
        for (int ni = 0; ni < 8; ++ni) {
            int n0 = wn*64 + ni*8 + l4*2;
            float s0 = fmaxf(acc[mi][ni][0] + sb2[n0],     0.f)*m1
                     + fmaxf(acc[mi][ni][2] + sb2[n0],     0.f)*m2;
            float s1 = fmaxf(acc[mi][ni][1] + sb2[n0 + 1], 0.f)*m1
                     + fmaxf(acc[mi][ni][3] + sb2[n0 + 1], 0.f)*m2;
            #pragma unroll
            for (int d = 4; d < 32; d <<= 1) {
                s0 += __shfl_xor_sync(0xFFFFFFFF, s0, d);
                s1 += __shfl_xor_sync(0xFFFFFFFF, s1, d);
            }
            if (g4 == 0)
                *(float2*)(g_S + (size_t)node_g*H + n0) = make_float2(s0, s1);
        }
    }
}

// ---------------------------------------------------------------------------
// k3: out = g_S @ W3 + b3 * valid_count   (BM=64, grid 256 to fill the chip)
// ---------------------------------------------------------------------------
__global__ __launch_bounds__(256, 2)
void k3_gemm(const int* __restrict__ nvalid, const float* __restrict__ W3,
             const float* __restrict__ b3, float* __restrict__ out)
{
    __shared__ float sS[64*36];
    __shared__ float sW[32*128];
    __shared__ float sb3[128];
    __shared__ float s_cnt[64];
    int tid = threadIdx.x, tx = tid & 15, ty = tid >> 4;
    int m0 = blockIdx.x * 64;
    if (tid < 128) sb3[tid] = b3[tid];
    if (tid < 64) {
        int c = 0;
        #pragma unroll
        for (int k = 0; k < K_; ++k) c += nvalid[(m0 + tid)*K_ + k];
        s_cnt[tid] = (float)c;
    }
    float acc[4][8];
    #pragma unroll
    for (int i = 0; i < 4; ++i)
        #pragma unroll
        for (int j = 0; j < 8; ++j) acc[i][j] = 0.f;
    for (int kc = 0; kc < 8; ++kc) {
        #pragma unroll
        for (int it = 0; it < 2; ++it) {
            int t4 = tid + 256*it, r = t4 >> 3, c4 = t4 & 7;
            *(float4*)(sS + r*36 + c4*4) = *(const float4*)(g_S + (m0 + r)*H + kc*32 + c4*4);
        }
        #pragma unroll
        for (int it = 0; it < 4; ++it) {
            int t4 = tid + 256*it, r = t4 >> 5, j4 = t4 & 31;
            *(float4*)(sW + r*128 + j4*4) = *(const float4*)(W3 + (kc*32 + r)*COUT + j4*4);
        }
        __syncthreads();
        #pragma unroll 8
        for (int kk = 0; kk < 32; ++kk) {
            float a[4], w[8];
            #pragma unroll
            for (int i = 0; i < 4; ++i) a[i] = sS[(ty + 16*i)*36 + kk];
            #pragma unroll
            for (int j = 0; j < 8; ++j) w[j] = sW[kk*128 + tx + 16*j];
            #pragma unroll
            for (int i = 0; i < 4; ++i)
                #pragma unroll
                for (int j = 0; j < 8; ++j) acc[i][j] += a[i]*w[j];
        }
        __syncthreads();
    }
    #pragma unroll
    for (int i = 0; i < 4; ++i) {
        int m = ty + 16*i;
        #pragma unroll
        for (int j = 0; j < 8; ++j) {
            int o = tx + 16*j;
            out[(m0 + m)*COUT + o] = acc[i][j] + sb3[o]*s_cnt[m];
        }
    }
}

// ---------------------------------------------------------------------------
extern "C" void kernel_launch(void* const* d_in, const int* in_sizes, int n_in,
                              void* d_out, int out_size)
{
    const float* feats  = (const float*)d_in[2];
    const int*   n_idxs = (const int*)  d_in[3];
    const int*   nvalid = (const int*)  d_in[4];
    const float* W1     = (const float*)d_in[5];
    const float* b1     = (const float*)d_in[6];
    const float* W2     = (const float*)d_in[7];
    const float* b2     = (const float*)d_in[8];
    const float* W3     = (const float*)d_in[9];
    const float* b3     = (const float*)d_in[10];
    float* out = (float*)d_out;

    cudaFuncSetAttribute(k2_edge, cudaFuncAttributeMaxDynamicSharedMemorySize, SMEM2);

    k0_prep<<<640, 256>>>(W2);
    k1_gemm<<<dim3(NODES/128, 4), 256>>>(feats, W1, b1);
    k2_edge<<<NODES/8, 256, SMEM2>>>(n_idxs, nvalid, b2);
    k3_gemm<<<NODES/64, 256>>>(nvalid, W3, b3, out);
}

// round 7
// speedup vs baseline: 2.1457x; 1.0427x over previous
#include <cuda_runtime.h>
#include <cuda_bf16.h>
#include <cstdint>

#define B_    4
#define N_    4096
#define K_    16
#define CIN   128
#define H     256
#define COUT  128
#define NODES (B_*N_)

__device__ float g_A [NODES*H];   // feats @ W1[:128,:] + b1
__device__ float g_Bm[NODES*H];   // feats @ W1[128:,:]
__device__ float g_S [NODES*H];   // sum_k mask*h2
// W2 split/packed: [chunk c:8][t][n:256][k:40] bf16
__device__ __align__(16) uint16_t g_W2p[8*2*256*40];
// W3 split/packed: [kc:2][t:2][n:128][k:136] bf16
__device__ __align__(16) uint16_t g_W3p[2*2*128*136];

// ---------------- helpers ----------------
__device__ __forceinline__ uint32_t smem_u32(const void* p) {
    uint32_t a;
    asm("{ .reg .u64 t; cvta.to.shared.u64 t, %1; cvt.u32.u64 %0, t; }" : "=r"(a) : "l"(p));
    return a;
}
__device__ __forceinline__ void mma_bf16(float* d, const uint32_t* a, const uint32_t* b) {
    asm volatile("mma.sync.aligned.m16n8k16.row.col.f32.bf16.bf16.f32 "
        "{%0,%1,%2,%3}, {%4,%5,%6,%7}, {%8,%9}, {%0,%1,%2,%3};"
        : "+f"(d[0]), "+f"(d[1]), "+f"(d[2]), "+f"(d[3])
        : "r"(a[0]), "r"(a[1]), "r"(a[2]), "r"(a[3]), "r"(b[0]), "r"(b[1]));
}
__device__ __forceinline__ void cp16(uint32_t sdst, const void* gsrc) {
    asm volatile("cp.async.cg.shared.global [%0], [%1], 16;" :: "r"(sdst), "l"(gsrc));
}
__device__ __forceinline__ void split2(float x, float y, uint32_t& hi, uint32_t& lo) {
    __nv_bfloat16 hx = __float2bfloat16(x), hy = __float2bfloat16(y);
    __nv_bfloat16 lx = __float2bfloat16(x - __bfloat162float(hx));
    __nv_bfloat16 ly = __float2bfloat16(y - __bfloat162float(hy));
    __nv_bfloat162 hp(hx, hy), lp(lx, ly);
    hi = *reinterpret_cast<uint32_t*>(&hp);
    lo = *reinterpret_cast<uint32_t*>(&lp);
}
__device__ __forceinline__ uint16_t split_pick(float w, int t) {
    __nv_bfloat16 hi = __float2bfloat16(w);
    if (t == 0) return *reinterpret_cast<uint16_t*>(&hi);
    __nv_bfloat16 lo = __float2bfloat16(w - __bfloat162float(hi));
    return *reinterpret_cast<uint16_t*>(&lo);
}

// ---------------------------------------------------------------------------
// k0: split/pack W2 and W3 (bounds-clean: no OOB reads)
// ---------------------------------------------------------------------------
__global__ void k0_prep(const float* __restrict__ W2, const float* __restrict__ W3)
{
    int i = blockIdx.x * 256 + threadIdx.x;
    if (i < 163840) {                                  // W2: [c][t][n][40]
        int kl = i % 40, n = (i / 40) % 256, t = (i / 10240) % 2, c = i / 20480;
        g_W2p[i] = (kl < 32) ? split_pick(W2[(c*32 + kl)*256 + n], t) : (uint16_t)0;
    } else if (i < 163840 + 69632) {                   // W3: [kc][t][n][136]
        int j = i - 163840;
        int k = j % 136, n = (j / 136) % 128, t = (j / 17408) % 2, kc = j / 34816;
        g_W3p[j] = (k < 128) ? split_pick(W3[(kc*128 + k)*128 + n], t) : (uint16_t)0;
    }
}

// ---------------------------------------------------------------------------
// k1: scalar fp32 GEMM (R5-proven): [16384x128]@[128x512] -> g_A(+b1) | g_Bm
// ---------------------------------------------------------------------------
__global__ __launch_bounds__(256, 2)
void k1_gemm(const float* __restrict__ feats, const float* __restrict__ W1,
             const float* __restrict__ b1)
{
    __shared__ float sF[128*36];
    __shared__ float sW[32*128];
    int tid = threadIdx.x, tx = tid & 15, ty = tid >> 4;
    int m0 = blockIdx.x * 128, by = blockIdx.y;
    const float* Wbase = W1 + ((by >> 1) ? (128*256) : 0) + (by & 1) * 128;
    float* Out = ((by >> 1) ? g_Bm : g_A) + (by & 1) * 128;
    float acc[8][8];
    #pragma unroll
    for (int i = 0; i < 8; ++i)
        #pragma unroll
        for (int j = 0; j < 8; ++j) acc[i][j] = 0.f;
    for (int kc = 0; kc < 4; ++kc) {
        #pragma unroll
        for (int it = 0; it < 4; ++it) {
            int t4 = tid + 256*it, r = t4 >> 3, c4 = t4 & 7;
            *(float4*)(sF + r*36 + c4*4) = *(const float4*)(feats + (m0 + r)*CIN + kc*32 + c4*4);
        }
        #pragma unroll
        for (int it = 0; it < 4; ++it) {
            int t4 = tid + 256*it, r = t4 >> 5, j4 = t4 & 31;
            *(float4*)(sW + r*128 + j4*4) = *(const float4*)(Wbase + (kc*32 + r)*256 + j4*4);
        }
        __syncthreads();
        #pragma unroll 8
        for (int kk = 0; kk < 32; ++kk) {
            float a[8], w[8];
            #pragma unroll
            for (int i = 0; i < 8; ++i) a[i] = sF[(ty + 16*i)*36 + kk];
            #pragma unroll
            for (int j = 0; j < 8; ++j) w[j] = sW[kk*128 + tx + 16*j];
            #pragma unroll
            for (int i = 0; i < 8; ++i)
                #pragma unroll
                for (int j = 0; j < 8; ++j) acc[i][j] += a[i]*w[j];
        }
        __syncthreads();
    }
    bool isA = (by < 2);
    #pragma unroll
    for (int i = 0; i < 8; ++i) {
        int m = m0 + ty + 16*i;
        #pragma unroll
        for (int j = 0; j < 8; ++j) {
            float bias = isA ? b1[(by & 1)*128 + tx + 16*j] : 0.f;
            Out[m*H + tx + 16*j] = acc[i][j] + bias;
        }
    }
}

// ---------------------------------------------------------------------------
// k2: edge MLP layer-2 (R5-proven HMMA)
// ---------------------------------------------------------------------------
#define OFF_H1HI 0
#define OFF_H1LO 67584
#define OFF_W    135168
#define OFF_B2   217088
#define OFF_SIDX 218112
#define OFF_SVAL 218624
#define SMEM2    219136

__global__ __launch_bounds__(256, 1)
void k2_edge(const int* __restrict__ n_idxs, const int* __restrict__ nvalid,
             const float* __restrict__ b2)
{
    extern __shared__ char smem[];
    uint16_t* sh1hi = (uint16_t*)(smem + OFF_H1HI);   // [128][264]
    uint16_t* sh1lo = (uint16_t*)(smem + OFF_H1LO);
    float*    sb2   = (float*)(smem + OFF_B2);
    int*      sidx  = (int*)(smem + OFF_SIDX);
    float*    sval  = (float*)(smem + OFF_SVAL);
    uint32_t  swbase = smem_u32(smem) + OFF_W;

    int tid = threadIdx.x, lane = tid & 31, wid = tid >> 5;
    int wm = wid >> 2, wn = wid & 3;
    int node0 = blockIdx.x * 8;

    #pragma unroll
    for (int s = 0; s < 2; ++s) {
        const char* src = (const char*)g_W2p + s*40960 + tid*16;
        uint32_t dst = swbase + s*40960 + tid*16;
        #pragma unroll
        for (int it = 0; it < 10; ++it)
            cp16(dst + it*4096, src + it*4096);
        asm volatile("cp.async.commit_group;" ::: "memory");
    }

    if (tid < 128) {
        sidx[tid] = n_idxs[node0*K_ + tid];
        sval[tid] = nvalid[node0*K_ + tid] ? 1.f : 0.f;
    }
    sb2[tid] = b2[tid];
    __syncthreads();

    {
        int e = tid >> 1, cb = (tid & 1) * 128;
        int node = node0 + (e >> 4);
        int gn = (node >> 12) * N_ + sidx[e];
        const float* ar = g_A  + (size_t)node * H + cb;
        const float* br = g_Bm + (size_t)gn   * H + cb;
        uint16_t* ph = sh1hi + e*264 + cb;
        uint16_t* pl = sh1lo + e*264 + cb;
        #pragma unroll
        for (int j = 0; j < 32; ++j) {
            float4 av = *(const float4*)(ar + 4*j);
            float4 bv = *(const float4*)(br + 4*j);
            float h0 = fmaxf(av.x + bv.x, 0.f), h1 = fmaxf(av.y + bv.y, 0.f);
            float h2 = fmaxf(av.z + bv.z, 0.f), h3 = fmaxf(av.w + bv.w, 0.f);
            uint32_t hi01, lo01, hi23, lo23;
            split2(h0, h1, hi01, lo01);
            split2(h2, h3, hi23, lo23);
            *(uint32_t*)(ph + 4*j)     = hi01;
            *(uint32_t*)(ph + 4*j + 2) = hi23;
            *(uint32_t*)(pl + 4*j)     = lo01;
            *(uint32_t*)(pl + 4*j + 2) = lo23;
        }
    }

    float acc[4][8][4];
    #pragma unroll
    for (int mi = 0; mi < 4; ++mi)
        #pragma unroll
        for (int ni = 0; ni < 8; ++ni)
            #pragma unroll
            for (int q = 0; q < 4; ++q) acc[mi][ni][q] = 0.f;

    int g4 = lane >> 2, l4 = lane & 3;

    for (int c = 0; c < 8; ++c) {
        if (c == 7) asm volatile("cp.async.wait_group 0;" ::: "memory");
        else        asm volatile("cp.async.wait_group 1;" ::: "memory");
        __syncthreads();

        const uint16_t* sWh = (const uint16_t*)(smem + OFF_W + (c & 1)*40960);
        const uint16_t* sWl = sWh + 10240;

        #pragma unroll
        for (int ks = 0; ks < 2; ++ks) {
            int kk = c*32 + ks*16 + l4*2;
            uint32_t ah[4][4], al[4][4], bb[8][2];
            #pragma unroll
            for (int mi = 0; mi < 4; ++mi) {
                const uint16_t* pa = sh1hi + (wm*64 + mi*16 + g4)*264 + kk;
                ah[mi][0] = *(const uint32_t*)pa;
                ah[mi][1] = *(const uint32_t*)(pa + 8*264);
                ah[mi][2] = *(const uint32_t*)(pa + 8);
                ah[mi][3] = *(const uint32_t*)(pa + 8*264 + 8);
            }
            #pragma unroll
            for (int ni = 0; ni < 8; ++ni) {
                const uint16_t* p = sWh + (wn*64 + ni*8 + g4)*40 + ks*16 + l4*2;
                bb[ni][0] = *(const uint32_t*)p;
                bb[ni][1] = *(const uint32_t*)(p + 8);
            }
            #pragma unroll
            for (int mi = 0; mi < 4; ++mi)
                #pragma unroll
                for (int ni = 0; ni < 8; ++ni)
                    mma_bf16(acc[mi][ni], ah[mi], bb[ni]);
            #pragma unroll
            for (int mi = 0; mi < 4; ++mi) {
                const uint16_t* pb = sh1lo + (wm*64 + mi*16 + g4)*264 + kk;
                al[mi][0] = *(const uint32_t*)pb;
                al[mi][1] = *(const uint32_t*)(pb + 8*264);
                al[mi][2] = *(const uint32_t*)(pb + 8);
                al[mi][3] = *(const uint32_t*)(pb + 8*264 + 8);
            }
            #pragma unroll
            for (int mi = 0; mi < 4; ++mi)
                #pragma unroll
                for (int ni = 0; ni < 8; ++ni)
                    mma_bf16(acc[mi][ni], al[mi], bb[ni]);
            #pragma unroll
            for (int ni = 0; ni < 8; ++ni) {
                const uint16_t* q = sWl + (wn*64 + ni*8 + g4)*40 + ks*16 + l4*2;
                bb[ni][0] = *(const uint32_t*)q;
                bb[ni][1] = *(const uint32_t*)(q + 8);
            }
            #pragma unroll
            for (int mi = 0; mi < 4; ++mi)
                #pragma unroll
                for (int ni = 0; ni < 8; ++ni)
                    mma_bf16(acc[mi][ni], ah[mi], bb[ni]);
        }
        __syncthreads();
        if (c < 6) {
            const char* src = (const char*)g_W2p + (c + 2)*40960 + tid*16;
            uint32_t dst = swbase + (c & 1)*40960 + tid*16;
            #pragma unroll
            for (int it = 0; it < 10; ++it)
                cp16(dst + it*4096, src + it*4096);
            asm volatile("cp.async.commit_group;" ::: "memory");
        }
    }

    #pragma unroll
    for (int mi = 0; mi < 4; ++mi) {
        int node_l = wm*4 + mi;
        float m1 = sval[node_l*16 + g4];
        float m2 = sval[node_l*16 + g4 + 8];
        int node_g = node0 + node_l;
        #pragma unroll
        for (int ni = 0; ni < 8; ++ni) {
            int n0 = wn*64 + ni*8 + l4*2;
            float s0 = fmaxf(acc[mi][ni][0] + sb2[n0],     0.f)*m1
                     + fmaxf(acc[mi][ni][2] + sb2[n0],     0.f)*m2;
            float s1 = fmaxf(acc[mi][ni][1] + sb2[n0 + 1], 0.f)*m1
                     + fmaxf(acc[mi][ni][3] + sb2[n0 + 1], 0.f)*m2;
            #pragma unroll
            for (int d = 4; d < 32; d <<= 1) {
                s0 += __shfl_xor_sync(0xFFFFFFFF, s0, d);
                s1 += __shfl_xor_sync(0xFFFFFFFF, s1, d);
            }
            if (g4 == 0)
                *(float2*)(g_S + (size_t)node_g*H + n0) = make_float2(s0, s1);
        }
    }
}

// ---------------------------------------------------------------------------
// k3 (HMMA, k2-clone structure): out = g_S @ W3 + b3*cnt, grid 128
// A resident full-k (stride 264, k2-proven); W3 streamed in 2 chunks.
// ---------------------------------------------------------------------------
#define OFF3_A   0          // hi[128][264] + lo[128][264] = 135168
#define OFF3_W   135168     // one chunk [t][128][136] = 69632
#define OFF3_B3  204800
#define OFF3_CNT 205312
#define SMEM3    205824

__global__ __launch_bounds__(256, 1)
void k3_hmma(const int* __restrict__ nvalid, const float* __restrict__ b3,
             float* __restrict__ out)
{
    extern __shared__ char sm[];
    uint16_t* sAhi = (uint16_t*)(sm + OFF3_A);
    uint16_t* sAlo = sAhi + 128*264;
    float*    sb3  = (float*)(sm + OFF3_B3);
    float*    scnt = (float*)(sm + OFF3_CNT);
    uint32_t  swb  = smem_u32(sm);

    int tid = threadIdx.x, lane = tid & 31, wid = tid >> 5;
    int wm = wid >> 2, wn = wid & 3, g4 = lane >> 2, l4 = lane & 3;
    int m0 = blockIdx.x * 128;

    // stream W3 chunk 0 (k 0..127, hi+lo): 69632 B = 17 x 16B/thread
    {
        const char* src = (const char*)g_W3p + tid*16;
        uint32_t dst = swb + OFF3_W + tid*16;
        #pragma unroll
        for (int it = 0; it < 17; ++it) cp16(dst + it*4096, src + it*4096);
        asm volatile("cp.async.commit_group;" ::: "memory");
    }
    if (tid < 128) {
        sb3[tid] = b3[tid];
        int c = 0;
        #pragma unroll
        for (int k = 0; k < K_; ++k) c += nvalid[(m0 + tid)*K_ + k];
        scnt[tid] = (float)c;
    }

    // build A (full k=256): thread -> row tid/2, k-half (tid&1)*128
    {
        int r = tid >> 1, kb = (tid & 1) * 128;
        const float* fr = g_S + (size_t)(m0 + r)*H + kb;
        uint16_t* ph = sAhi + r*264 + kb;
        uint16_t* pl = sAlo + r*264 + kb;
        #pragma unroll
        for (int j = 0; j < 32; ++j) {
            float4 v = *(const float4*)(fr + 4*j);
            uint32_t h01, l01, h23, l23;
            split2(v.x, v.y, h01, l01);
            split2(v.z, v.w, h23, l23);
            *(uint32_t*)(ph + 4*j)     = h01;
            *(uint32_t*)(ph + 4*j + 2) = h23;
            *(uint32_t*)(pl + 4*j)     = l01;
            *(uint32_t*)(pl + 4*j + 2) = l23;
        }
    }
    asm volatile("cp.async.wait_group 0;" ::: "memory");
    __syncthreads();

    float acc[4][4][4];
    #pragma unroll
    for (int mi = 0; mi < 4; ++mi)
        #pragma unroll
        for (int ni = 0; ni < 4; ++ni)
            #pragma unroll
            for (int q = 0; q < 4; ++q) acc[mi][ni][q] = 0.f;

    for (int kc = 0; kc < 2; ++kc) {
        const uint16_t* sW  = (const uint16_t*)(sm + OFF3_W);
        const uint16_t* sWl = sW + 17408;

        #pragma unroll
        for (int ks = 0; ks < 8; ++ks) {
            int kk = ks*16 + l4*2;          // local k within chunk (for W)
            int ka = kc*128 + kk;           // global k (for A)
            uint32_t ah[4][4], al[4][4], bb[4][2];
            #pragma unroll
            for (int mi = 0; mi < 4; ++mi) {
                const uint16_t* pa = sAhi + (wm*64 + mi*16 + g4)*264 + ka;
                ah[mi][0] = *(const uint32_t*)pa;
                ah[mi][1] = *(const uint32_t*)(pa + 8*264);
                ah[mi][2] = *(const uint32_t*)(pa + 8);
                ah[mi][3] = *(const uint32_t*)(pa + 8*264 + 8);
                const uint16_t* pb = sAlo + (wm*64 + mi*16 + g4)*264 + ka;
                al[mi][0] = *(const uint32_t*)pb;
                al[mi][1] = *(const uint32_t*)(pb + 8*264);
                al[mi][2] = *(const uint32_t*)(pb + 8);
                al[mi][3] = *(const uint32_t*)(pb + 8*264 + 8);
            }
            #pragma unroll
            for (int ni = 0; ni < 4; ++ni) {
                const uint16_t* p = sW + (wn*32 + ni*8 + g4)*136 + kk;
                bb[ni][0] = *(const uint32_t*)p;
                bb[ni][1] = *(const uint32_t*)(p + 8);
            }
            #pragma unroll
            for (int mi = 0; mi < 4; ++mi)
                #pragma unroll
                for (int ni = 0; ni < 4; ++ni) {
                    mma_bf16(acc[mi][ni], ah[mi], bb[ni]);
                    mma_bf16(acc[mi][ni], al[mi], bb[ni]);
                }
            #pragma unroll
            for (int ni = 0; ni < 4; ++ni) {
                const uint16_t* q = sWl + (wn*32 + ni*8 + g4)*136 + kk;
                bb[ni][0] = *(const uint32_t*)q;
                bb[ni][1] = *(const uint32_t*)(q + 8);
            }
            #pragma unroll
            for (int mi = 0; mi < 4; ++mi)
                #pragma unroll
                for (int ni = 0; ni < 4; ++ni)
                    mma_bf16(acc[mi][ni], ah[mi], bb[ni]);
        }
        __syncthreads();                    // all reads of W buffer done
        if (kc == 0) {                      // stream chunk 1 into same buffer
            const char* src = (const char*)g_W3p + 69632 + tid*16;
            uint32_t dst = swb + OFF3_W + tid*16;
            #pragma unroll
            for (int it = 0; it < 17; ++it) cp16(dst + it*4096, src + it*4096);
            asm volatile("cp.async.commit_group;" ::: "memory");
            asm volatile("cp.async.wait_group 0;" ::: "memory");
            __syncthreads();
        }
    }

    #pragma unroll
    for (int mi = 0; mi < 4; ++mi) {
        int m = wm*64 + mi*16 + g4;
        #pragma unroll
        for (int ni = 0; ni < 4; ++ni) {
            int n0 = wn*32 + ni*8 + l4*2;
            float b0 = sb3[n0], bv1 = sb3[n0 + 1];
            *(float2*)(out + (size_t)(m0 + m)*COUT + n0) =
                make_float2(acc[mi][ni][0] + b0*scnt[m], acc[mi][ni][1] + bv1*scnt[m]);
            *(float2*)(out + (size_t)(m0 + m + 8)*COUT + n0) =
                make_float2(acc[mi][ni][2] + b0*scnt[m + 8], acc[mi][ni][3] + bv1*scnt[m + 8]);
        }
    }
}

// ---------------------------------------------------------------------------
extern "C" void kernel_launch(void* const* d_in, const int* in_sizes, int n_in,
                              void* d_out, int out_size)
{
    const float* feats  = (const float*)d_in[2];
    const int*   n_idxs = (const int*)  d_in[3];
    const int*   nvalid = (const int*)  d_in[4];
    const float* W1     = (const float*)d_in[5];
    const float* b1     = (const float*)d_in[6];
    const float* W2     = (const float*)d_in[7];
    const float* b2     = (const float*)d_in[8];
    const float* W3     = (const float*)d_in[9];
    const float* b3     = (const float*)d_in[10];
    float* out = (float*)d_out;

    cudaFuncSetAttribute(k2_edge, cudaFuncAttributeMaxDynamicSharedMemorySize, SMEM2);
    cudaFuncSetAttribute(k3_hmma, cudaFuncAttributeMaxDynamicSharedMemorySize, SMEM3);

    k0_prep<<<912, 256>>>(W2, W3);
    k1_gemm<<<dim3(NODES/128, 4), 256>>>(feats, W1, b1);
    k2_edge<<<NODES/8, 256, SMEM2>>>(n_idxs, nvalid, b2);
    k3_hmma<<<128, 256, SMEM3>>>(nvalid, b3, out);
}

// round 8
// speedup vs baseline: 2.3247x; 1.0834x over previous
#include <cuda_runtime.h>
#include <cuda_bf16.h>
#include <cstdint>

#define B_    4
#define N_    4096
#define K_    16
#define CIN   128
#define H     256
#define COUT  128
#define NODES (B_*N_)

__device__ float g_A [NODES*H];   // feats @ W1[:128,:] + b1
__device__ float g_Bm[NODES*H];   // feats @ W1[128:,:]
__device__ float g_S [NODES*H];   // sum_k mask*h2
// W1 split/packed: [hf:2][t:2][n:256][k:136] bf16  (139264 elems)
__device__ __align__(16) uint16_t g_W1p[2*2*256*136];
// W2 split/packed: [chunk c:8][t][n:256][k:40] bf16
__device__ __align__(16) uint16_t g_W2p[8*2*256*40];
// W3 split/packed: [kc:2][t:2][n:128][k:136] bf16
__device__ __align__(16) uint16_t g_W3p[2*2*128*136];

// ---------------- helpers ----------------
__device__ __forceinline__ uint32_t smem_u32(const void* p) {
    uint32_t a;
    asm("{ .reg .u64 t; cvta.to.shared.u64 t, %1; cvt.u32.u64 %0, t; }" : "=r"(a) : "l"(p));
    return a;
}
__device__ __forceinline__ void mma_bf16(float* d, const uint32_t* a, const uint32_t* b) {
    asm volatile("mma.sync.aligned.m16n8k16.row.col.f32.bf16.bf16.f32 "
        "{%0,%1,%2,%3}, {%4,%5,%6,%7}, {%8,%9}, {%0,%1,%2,%3};"
        : "+f"(d[0]), "+f"(d[1]), "+f"(d[2]), "+f"(d[3])
        : "r"(a[0]), "r"(a[1]), "r"(a[2]), "r"(a[3]), "r"(b[0]), "r"(b[1]));
}
__device__ __forceinline__ void cp16(uint32_t sdst, const void* gsrc) {
    asm volatile("cp.async.cg.shared.global [%0], [%1], 16;" :: "r"(sdst), "l"(gsrc));
}
__device__ __forceinline__ void split2(float x, float y, uint32_t& hi, uint32_t& lo) {
    __nv_bfloat16 hx = __float2bfloat16(x), hy = __float2bfloat16(y);
    __nv_bfloat16 lx = __float2bfloat16(x - __bfloat162float(hx));
    __nv_bfloat16 ly = __float2bfloat16(y - __bfloat162float(hy));
    __nv_bfloat162 hp(hx, hy), lp(lx, ly);
    hi = *reinterpret_cast<uint32_t*>(&hp);
    lo = *reinterpret_cast<uint32_t*>(&lp);
}
__device__ __forceinline__ uint16_t split_pick(float w, int t) {
    __nv_bfloat16 hi = __float2bfloat16(w);
    if (t == 0) return *reinterpret_cast<uint16_t*>(&hi);
    __nv_bfloat16 lo = __float2bfloat16(w - __bfloat162float(hi));
    return *reinterpret_cast<uint16_t*>(&lo);
}

// ---------------------------------------------------------------------------
// k0: split/pack W2, W1, W3 (bounds-clean; every segment exactly sized)
// ---------------------------------------------------------------------------
__global__ void k0_prep(const float* __restrict__ W1, const float* __restrict__ W2,
                        const float* __restrict__ W3)
{
    int i = blockIdx.x * 256 + threadIdx.x;
    if (i < 163840) {                                  // W2: [c][t][n][40]
        int kl = i % 40, n = (i / 40) % 256, t = (i / 10240) % 2, c = i / 20480;
        g_W2p[i] = (kl < 32) ? split_pick(W2[(c*32 + kl)*256 + n], t) : (uint16_t)0;
    } else if (i < 163840 + 139264) {                  // W1: [hf][t][n][136]
        int j = i - 163840;
        int k = j % 136, n = (j / 136) % 256, t = (j / 34816) % 2, hf = j / 69632;
        g_W1p[j] = (k < 128) ? split_pick(W1[(hf*128 + k)*256 + n], t) : (uint16_t)0;
    } else if (i < 163840 + 139264 + 69632) {          // W3: [kc][t][n][136]
        int j = i - 303104;
        int k = j % 136, n = (j / 136) % 128, t = (j / 17408) % 2, kc = j / 34816;
        g_W3p[j] = (k < 128) ? split_pick(W3[(kc*128 + k)*128 + n], t) : (uint16_t)0;
    }
}

// ---------------------------------------------------------------------------
// k1 (HMMA): [16384x128] @ [128x256] -> g_A(+b1) | g_Bm, grid (128, 2)
// ---------------------------------------------------------------------------
#define OFF1_W  0          // [t][256][136] bf16 = 139264 B
#define OFF1_A  139264     // hi[128][136] + lo = 69632 B
#define OFF1_B1 208896     // 256 floats
#define SMEM1   209920

__global__ __launch_bounds__(256, 1)
void k1_hmma(const float* __restrict__ feats, const float* __restrict__ b1)
{
    extern __shared__ char sm1[];
    uint16_t* sW   = (uint16_t*)(sm1 + OFF1_W);
    uint16_t* sAhi = (uint16_t*)(sm1 + OFF1_A);
    uint16_t* sAlo = sAhi + 128*136;
    float*    sb1  = (float*)(sm1 + OFF1_B1);
    uint32_t  swb  = smem_u32(sm1);

    int tid = threadIdx.x, lane = tid & 31, wid = tid >> 5;
    int wm = wid >> 2, wn = wid & 3, g4 = lane >> 2, l4 = lane & 3;
    int m0 = blockIdx.x * 128, hf = blockIdx.y;

    // stream W half (hi+lo): 139264 B = 34 x 16B/thread
    {
        const char* src = (const char*)(g_W1p + hf*69632) + tid*16;
        uint32_t dst = swb + OFF1_W + tid*16;
        #pragma unroll
        for (int it = 0; it < 34; ++it) cp16(dst + it*4096, src + it*4096);
        asm volatile("cp.async.commit_group;" ::: "memory");
    }
    sb1[tid] = (hf == 0) ? b1[tid] : 0.f;

    // build A hi/lo: thread -> row tid/2, k-half (tid&1)*64
    {
        int r = tid >> 1, kb = (tid & 1) * 64;
        const float* fr = feats + (size_t)(m0 + r)*CIN + kb;
        uint16_t* ph = sAhi + r*136 + kb;
        uint16_t* pl = sAlo + r*136 + kb;
        #pragma unroll
        for (int j = 0; j < 16; ++j) {
            float4 v = *(const float4*)(fr + 4*j);
            uint32_t h01, l01, h23, l23;
            split2(v.x, v.y, h01, l01);
            split2(v.z, v.w, h23, l23);
            *(uint32_t*)(ph + 4*j)     = h01;
            *(uint32_t*)(ph + 4*j + 2) = h23;
            *(uint32_t*)(pl + 4*j)     = l01;
            *(uint32_t*)(pl + 4*j + 2) = l23;
        }
    }
    asm volatile("cp.async.wait_group 0;" ::: "memory");
    __syncthreads();

    float acc[4][8][4];
    #pragma unroll
    for (int mi = 0; mi < 4; ++mi)
        #pragma unroll
        for (int ni = 0; ni < 8; ++ni)
            #pragma unroll
            for (int q = 0; q < 4; ++q) acc[mi][ni][q] = 0.f;

    const uint16_t* sWl = sW + 34816;
    #pragma unroll
    for (int ks = 0; ks < 8; ++ks) {
        int kk = ks*16 + l4*2;
        uint32_t ah[4][4], al[4][4], bb[8][2];
        #pragma unroll
        for (int mi = 0; mi < 4; ++mi) {
            const uint16_t* pa = sAhi + (wm*64 + mi*16 + g4)*136 + kk;
            ah[mi][0] = *(const uint32_t*)pa;
            ah[mi][1] = *(const uint32_t*)(pa + 8*136);
            ah[mi][2] = *(const uint32_t*)(pa + 8);
            ah[mi][3] = *(const uint32_t*)(pa + 8*136 + 8);
            const uint16_t* pb = sAlo + (wm*64 + mi*16 + g4)*136 + kk;
            al[mi][0] = *(const uint32_t*)pb;
            al[mi][1] = *(const uint32_t*)(pb + 8*136);
            al[mi][2] = *(const uint32_t*)(pb + 8);
            al[mi][3] = *(const uint32_t*)(pb + 8*136 + 8);
        }
        #pragma unroll
        for (int ni = 0; ni < 8; ++ni) {
            const uint16_t* p = sW + (wn*64 + ni*8 + g4)*136 + kk;
            bb[ni][0] = *(const uint32_t*)p;
            bb[ni][1] = *(const uint32_t*)(p + 8);
        }
        #pragma unroll
        for (int mi = 0; mi < 4; ++mi)
            #pragma unroll
            for (int ni = 0; ni < 8; ++ni) {
                mma_bf16(acc[mi][ni], ah[mi], bb[ni]);
                mma_bf16(acc[mi][ni], al[mi], bb[ni]);
            }
        #pragma unroll
        for (int ni = 0; ni < 8; ++ni) {
            const uint16_t* q = sWl + (wn*64 + ni*8 + g4)*136 + kk;
            bb[ni][0] = *(const uint32_t*)q;
            bb[ni][1] = *(const uint32_t*)(q + 8);
        }
        #pragma unroll
        for (int mi = 0; mi < 4; ++mi)
            #pragma unroll
            for (int ni = 0; ni < 8; ++ni)
                mma_bf16(acc[mi][ni], ah[mi], bb[ni]);
    }

    float* Out = hf ? g_Bm : g_A;
    #pragma unroll
    for (int mi = 0; mi < 4; ++mi) {
        int m = wm*64 + mi*16 + g4;
        #pragma unroll
        for (int ni = 0; ni < 8; ++ni) {
            int n0 = wn*64 + ni*8 + l4*2;
            float b0 = sb1[n0], bv1 = sb1[n0 + 1];
            *(float2*)(Out + (size_t)(m0 + m)*H + n0) =
                make_float2(acc[mi][ni][0] + b0, acc[mi][ni][1] + bv1);
            *(float2*)(Out + (size_t)(m0 + m + 8)*H + n0) =
                make_float2(acc[mi][ni][2] + b0, acc[mi][ni][3] + bv1);
        }
    }
}

// ---------------------------------------------------------------------------
// k2: edge MLP layer-2 (R5/R7-proven HMMA)
// ---------------------------------------------------------------------------
#define OFF_H1HI 0
#define OFF_H1LO 67584
#define OFF_W    135168
#define OFF_B2   217088
#define OFF_SIDX 218112
#define OFF_SVAL 218624
#define SMEM2    219136

__global__ __launch_bounds__(256, 1)
void k2_edge(const int* __restrict__ n_idxs, const int* __restrict__ nvalid,
             const float* __restrict__ b2)
{
    extern __shared__ char smem[];
    uint16_t* sh1hi = (uint16_t*)(smem + OFF_H1HI);   // [128][264]
    uint16_t* sh1lo = (uint16_t*)(smem + OFF_H1LO);
    float*    sb2   = (float*)(smem + OFF_B2);
    int*      sidx  = (int*)(smem + OFF_SIDX);
    float*    sval  = (float*)(smem + OFF_SVAL);
    uint32_t  swbase = smem_u32(smem) + OFF_W;

    int tid = threadIdx.x, lane = tid & 31, wid = tid >> 5;
    int wm = wid >> 2, wn = wid & 3;
    int node0 = blockIdx.x * 8;

    #pragma unroll
    for (int s = 0; s < 2; ++s) {
        const char* src = (const char*)g_W2p + s*40960 + tid*16;
        uint32_t dst = swbase + s*40960 + tid*16;
        #pragma unroll
        for (int it = 0; it < 10; ++it)
            cp16(dst + it*4096, src + it*4096);
        asm volatile("cp.async.commit_group;" ::: "memory");
    }

    if (tid < 128) {
        sidx[tid] = n_idxs[node0*K_ + tid];
        sval[tid] = nvalid[node0*K_ + tid] ? 1.f : 0.f;
    }
    sb2[tid] = b2[tid];
    __syncthreads();

    {
        int e = tid >> 1, cb = (tid & 1) * 128;
        int node = node0 + (e >> 4);
        int gn = (node >> 12) * N_ + sidx[e];
        const float* ar = g_A  + (size_t)node * H + cb;
        const float* br = g_Bm + (size_t)gn   * H + cb;
        uint16_t* ph = sh1hi + e*264 + cb;
        uint16_t* pl = sh1lo + e*264 + cb;
        #pragma unroll
        for (int j = 0; j < 32; ++j) {
            float4 av = *(const float4*)(ar + 4*j);
            float4 bv = *(const float4*)(br + 4*j);
            float h0 = fmaxf(av.x + bv.x, 0.f), h1 = fmaxf(av.y + bv.y, 0.f);
            float h2 = fmaxf(av.z + bv.z, 0.f), h3 = fmaxf(av.w + bv.w, 0.f);
            uint32_t hi01, lo01, hi23, lo23;
            split2(h0, h1, hi01, lo01);
            split2(h2, h3, hi23, lo23);
            *(uint32_t*)(ph + 4*j)     = hi01;
            *(uint32_t*)(ph + 4*j + 2) = hi23;
            *(uint32_t*)(pl + 4*j)     = lo01;
            *(uint32_t*)(pl + 4*j + 2) = lo23;
        }
    }

    float acc[4][8][4];
    #pragma unroll
    for (int mi = 0; mi < 4; ++mi)
        #pragma unroll
        for (int ni = 0; ni < 8; ++ni)
            #pragma unroll
            for (int q = 0; q < 4; ++q) acc[mi][ni][q] = 0.f;

    int g4 = lane >> 2, l4 = lane & 3;

    for (int c = 0; c < 8; ++c) {
        if (c == 7) asm volatile("cp.async.wait_group 0;" ::: "memory");
        else        asm volatile("cp.async.wait_group 1;" ::: "memory");
        __syncthreads();

        const uint16_t* sWh = (const uint16_t*)(smem + OFF_W + (c & 1)*40960);
        const uint16_t* sWl = sWh + 10240;

        #pragma unroll
        for (int ks = 0; ks < 2; ++ks) {
            int kk = c*32 + ks*16 + l4*2;
            uint32_t ah[4][4], al[4][4], bb[8][2];
            #pragma unroll
            for (int mi = 0; mi < 4; ++mi) {
                const uint16_t* pa = sh1hi + (wm*64 + mi*16 + g4)*264 + kk;
                ah[mi][0] = *(const uint32_t*)pa;
                ah[mi][1] = *(const uint32_t*)(pa + 8*264);
                ah[mi][2] = *(const uint32_t*)(pa + 8);
                ah[mi][3] = *(const uint32_t*)(pa + 8*264 + 8);
            }
            #pragma unroll
            for (int ni = 0; ni < 8; ++ni) {
                const uint16_t* p = sWh + (wn*64 + ni*8 + g4)*40 + ks*16 + l4*2;
                bb[ni][0] = *(const uint32_t*)p;
                bb[ni][1] = *(const uint32_t*)(p + 8);
            }
            #pragma unroll
            for (int mi = 0; mi < 4; ++mi)
                #pragma unroll
                for (int ni = 0; ni < 8; ++ni)
                    mma_bf16(acc[mi][ni], ah[mi], bb[ni]);
            #pragma unroll
            for (int mi = 0; mi < 4; ++mi) {
                const uint16_t* pb = sh1lo + (wm*64 + mi*16 + g4)*264 + kk;
                al[mi][0] = *(const uint32_t*)pb;
                al[mi][1] = *(const uint32_t*)(pb + 8*264);
                al[mi][2] = *(const uint32_t*)(pb + 8);
                al[mi][3] = *(const uint32_t*)(pb + 8*264 + 8);
            }
            #pragma unroll
            for (int mi = 0; mi < 4; ++mi)
                #pragma unroll
                for (int ni = 0; ni < 8; ++ni)
                    mma_bf16(acc[mi][ni], al[mi], bb[ni]);
            #pragma unroll
            for (int ni = 0; ni < 8; ++ni) {
                const uint16_t* q = sWl + (wn*64 + ni*8 + g4)*40 + ks*16 + l4*2;
                bb[ni][0] = *(const uint32_t*)q;
                bb[ni][1] = *(const uint32_t*)(q + 8);
            }
            #pragma unroll
            for (int mi = 0; mi < 4; ++mi)
                #pragma unroll
                for (int ni = 0; ni < 8; ++ni)
                    mma_bf16(acc[mi][ni], ah[mi], bb[ni]);
        }
        __syncthreads();
        if (c < 6) {
            const char* src = (const char*)g_W2p + (c + 2)*40960 + tid*16;
            uint32_t dst = swbase + (c & 1)*40960 + tid*16;
            #pragma unroll
            for (int it = 0; it < 10; ++it)
                cp16(dst + it*4096, src + it*4096);
            asm volatile("cp.async.commit_group;" ::: "memory");
        }
    }

    #pragma unroll
    for (int mi = 0; mi < 4; ++mi) {
        int node_l = wm*4 + mi;
        float m1 = sval[node_l*16 + g4];
        float m2 = sval[node_l*16 + g4 + 8];
        int node_g = node0 + node_l;
        #pragma unroll
        for (int ni = 0; ni < 8; ++ni) {
            int n0 = wn*64 + ni*8 + l4*2;
            float s0 = fmaxf(acc[mi][ni][0] + sb2[n0],     0.f)*m1
                     + fmaxf(acc[mi][ni][2] + sb2[n0],     0.f)*m2;
            float s1 = fmaxf(acc[mi][ni][1] + sb2[n0 + 1], 0.f)*m1
                     + fmaxf(acc[mi][ni][3] + sb2[n0 + 1], 0.f)*m2;
            #pragma unroll
            for (int d = 4; d < 32; d <<= 1) {
                s0 += __shfl_xor_sync(0xFFFFFFFF, s0, d);
                s1 += __shfl_xor_sync(0xFFFFFFFF, s1, d);
            }
            if (g4 == 0)
                *(float2*)(g_S + (size_t)node_g*H + n0) = make_float2(s0, s1);
        }
    }
}

// ---------------------------------------------------------------------------
// k3 (HMMA, R7-proven): out = g_S @ W3 + b3*cnt, grid 128
// ---------------------------------------------------------------------------
#define OFF3_A   0          // hi[128][264] + lo[128][264] = 135168
#define OFF3_W   135168     // one chunk [t][128][136] = 69632
#define OFF3_B3  204800
#define OFF3_CNT 205312
#define SMEM3    205824

__global__ __launch_bounds__(256, 1)
void k3_hmma(const int* __restrict__ nvalid, const float* __restrict__ b3,
             float* __restrict__ out)
{
    extern __shared__ char sm3[];
    uint16_t* sAhi = (uint16_t*)(sm3 + OFF3_A);
    uint16_t* sAlo = sAhi + 128*264;
    float*    sb3  = (float*)(sm3 + OFF3_B3);
    float*    scnt = (float*)(sm3 + OFF3_CNT);
    uint32_t  swb  = smem_u32(sm3);

    int tid = threadIdx.x, lane = tid & 31, wid = tid >> 5;
    int wm = wid >> 2, wn = wid & 3, g4 = lane >> 2, l4 = lane & 3;
    int m0 = blockIdx.x * 128;

    {
        const char* src = (const char*)g_W3p + tid*16;
        uint32_t dst = swb + OFF3_W + tid*16;
        #pragma unroll
        for (int it = 0; it < 17; ++it) cp16(dst + it*4096, src + it*4096);
        asm volatile("cp.async.commit_group;" ::: "memory");
    }
    if (tid < 128) {
        sb3[tid] = b3[tid];
        int c = 0;
        #pragma unroll
        for (int k = 0; k < K_; ++k) c += nvalid[(m0 + tid)*K_ + k];
        scnt[tid] = (float)c;
    }

    {
        int r = tid >> 1, kb = (tid & 1) * 128;
        const float* fr = g_S + (size_t)(m0 + r)*H + kb;
        uint16_t* ph = sAhi + r*264 + kb;
        uint16_t* pl = sAlo + r*264 + kb;
        #pragma unroll
        for (int j = 0; j < 32; ++j) {
            float4 v = *(const float4*)(fr + 4*j);
            uint32_t h01, l01, h23, l23;
            split2(v.x, v.y, h01, l01);
            split2(v.z, v.w, h23, l23);
            *(uint32_t*)(ph + 4*j)     = h01;
            *(uint32_t*)(ph + 4*j + 2) = h23;
            *(uint32_t*)(pl + 4*j)     = l01;
            *(uint32_t*)(pl + 4*j + 2) = l23;
        }
    }
    asm volatile("cp.async.wait_group 0;" ::: "memory");
    __syncthreads();

    float acc[4][4][4];
    #pragma unroll
    for (int mi = 0; mi < 4; ++mi)
        #pragma unroll
        for (int ni = 0; ni < 4; ++ni)
            #pragma unroll
            for (int q = 0; q < 4; ++q) acc[mi][ni][q] = 0.f;

    for (int kc = 0; kc < 2; ++kc) {
        const uint16_t* sW  = (const uint16_t*)(sm3 + OFF3_W);
        const uint16_t* sWl = sW + 17408;

        #pragma unroll
        for (int ks = 0; ks < 8; ++ks) {
            int kk = ks*16 + l4*2;
            int ka = kc*128 + kk;
            uint32_t ah[4][4], al[4][4], bb[4][2];
            #pragma unroll
            for (int mi = 0; mi < 4; ++mi) {
                const uint16_t* pa = sAhi + (wm*64 + mi*16 + g4)*264 + ka;
                ah[mi][0] = *(const uint32_t*)pa;
                ah[mi][1] = *(const uint32_t*)(pa + 8*264);
                ah[mi][2] = *(const uint32_t*)(pa + 8);
                ah[mi][3] = *(const uint32_t*)(pa + 8*264 + 8);
                const uint16_t* pb = sAlo + (wm*64 + mi*16 + g4)*264 + ka;
                al[mi][0] = *(const uint32_t*)pb;
                al[mi][1] = *(const uint32_t*)(pb + 8*264);
                al[mi][2] = *(const uint32_t*)(pb + 8);
                al[mi][3] = *(const uint32_t*)(pb + 8*264 + 8);
            }
            #pragma unroll
            for (int ni = 0; ni < 4; ++ni) {
                const uint16_t* p = sW + (wn*32 + ni*8 + g4)*136 + kk;
                bb[ni][0] = *(const uint32_t*)p;
                bb[ni][1] = *(const uint32_t*)(p + 8);
            }
            #pragma unroll
            for (int mi = 0; mi < 4; ++mi)
                #pragma unroll
                for (int ni = 0; ni < 4; ++ni) {
                    mma_bf16(acc[mi][ni], ah[mi], bb[ni]);
                    mma_bf16(acc[mi][ni], al[mi], bb[ni]);
                }
            #pragma unroll
            for (int ni = 0; ni < 4; ++ni) {
                const uint16_t* q = sWl + (wn*32 + ni*8 + g4)*136 + kk;
                bb[ni][0] = *(const uint32_t*)q;
                bb[ni][1] = *(const uint32_t*)(q + 8);
            }
            #pragma unroll
            for (int mi = 0; mi < 4; ++mi)
                #pragma unroll
                for (int ni = 0; ni < 4; ++ni)
                    mma_bf16(acc[mi][ni], ah[mi], bb[ni]);
        }
        __syncthreads();
        if (kc == 0) {
            const char* src = (const char*)g_W3p + 69632 + tid*16;
            uint32_t dst = swb + OFF3_W + tid*16;
            #pragma unroll
            for (int it = 0; it < 17; ++it) cp16(dst + it*4096, src + it*4096);
            asm volatile("cp.async.commit_group;" ::: "memory");
            asm volatile("cp.async.wait_group 0;" ::: "memory");
            __syncthreads();
        }
    }

    #pragma unroll
    for (int mi = 0; mi < 4; ++mi) {
        int m = wm*64 + mi*16 + g4;
        #pragma unroll
        for (int ni = 0; ni < 4; ++ni) {
            int n0 = wn*32 + ni*8 + l4*2;
            float b0 = sb3[n0], bv1 = sb3[n0 + 1];
            *(float2*)(out + (size_t)(m0 + m)*COUT + n0) =
                make_float2(acc[mi][ni][0] + b0*scnt[m], acc[mi][ni][1] + bv1*scnt[m]);
            *(float2*)(out + (size_t)(m0 + m + 8)*COUT + n0) =
                make_float2(acc[mi][ni][2] + b0*scnt[m + 8], acc[mi][ni][3] + bv1*scnt[m + 8]);
        }
    }
}

// ---------------------------------------------------------------------------
extern "C" void kernel_launch(void* const* d_in, const int* in_sizes, int n_in,
                              void* d_out, int out_size)
{
    const float* feats  = (const float*)d_in[2];
    const int*   n_idxs = (const int*)  d_in[3];
    const int*   nvalid = (const int*)  d_in[4];
    const float* W1     = (const float*)d_in[5];
    const float* b1     = (const float*)d_in[6];
    const float* W2     = (const float*)d_in[7];
    const float* b2     = (const float*)d_in[8];
    const float* W3     = (const float*)d_in[9];
    const float* b3     = (const float*)d_in[10];
    float* out = (float*)d_out;

    cudaFuncSetAttribute(k1_hmma, cudaFuncAttributeMaxDynamicSharedMemorySize, SMEM1);
    cudaFuncSetAttribute(k2_edge, cudaFuncAttributeMaxDynamicSharedMemorySize, SMEM2);
    cudaFuncSetAttribute(k3_hmma, cudaFuncAttributeMaxDynamicSharedMemorySize, SMEM3);

    k0_prep<<<1456, 256>>>(W1, W2, W3);
    k1_hmma<<<dim3(128, 2), 256, SMEM1>>>(feats, b1);
    k2_edge<<<NODES/8, 256, SMEM2>>>(n_idxs, nvalid, b2);
    k3_hmma<<<128, 256, SMEM3>>>(nvalid, b3, out);
}

// round 9
// speedup vs baseline: 2.3653x; 1.0175x over previous
#include <cuda_runtime.h>
#include <cuda_bf16.h>
#include <cuda_fp16.h>
#include <cstdint>

#define B_    4
#define N_    4096
#define K_    16
#define CIN   128
#define H     256
#define COUT  128
#define NODES (B_*N_)

__device__ float g_A [NODES*H];   // feats @ W1[:128,:] + b1
__device__ float g_Bm[NODES*H];   // feats @ W1[128:,:]
__device__ float g_S [NODES*H];   // sum_k mask*h2
// W1 split/packed bf16: [hf:2][t:2][n:256][k:136]
__device__ __align__(16) uint16_t g_W1p[2*2*256*136];
// W2 packed fp16 (single precision term): [chunk c:8][n:256][k:40]
__device__ __align__(16) uint16_t g_W2h[8*256*40];
// W3 split/packed bf16: [kc:2][t:2][n:128][k:136]
__device__ __align__(16) uint16_t g_W3p[2*2*128*136];

// ---------------- helpers ----------------
__device__ __forceinline__ uint32_t smem_u32(const void* p) {
    uint32_t a;
    asm("{ .reg .u64 t; cvta.to.shared.u64 t, %1; cvt.u32.u64 %0, t; }" : "=r"(a) : "l"(p));
    return a;
}
__device__ __forceinline__ void mma_bf16(float* d, const uint32_t* a, const uint32_t* b) {
    asm volatile("mma.sync.aligned.m16n8k16.row.col.f32.bf16.bf16.f32 "
        "{%0,%1,%2,%3}, {%4,%5,%6,%7}, {%8,%9}, {%0,%1,%2,%3};"
        : "+f"(d[0]), "+f"(d[1]), "+f"(d[2]), "+f"(d[3])
        : "r"(a[0]), "r"(a[1]), "r"(a[2]), "r"(a[3]), "r"(b[0]), "r"(b[1]));
}
__device__ __forceinline__ void mma_f16(float* d, const uint32_t* a, const uint32_t* b) {
    asm volatile("mma.sync.aligned.m16n8k16.row.col.f32.f16.f16.f32 "
        "{%0,%1,%2,%3}, {%4,%5,%6,%7}, {%8,%9}, {%0,%1,%2,%3};"
        : "+f"(d[0]), "+f"(d[1]), "+f"(d[2]), "+f"(d[3])
        : "r"(a[0]), "r"(a[1]), "r"(a[2]), "r"(a[3]), "r"(b[0]), "r"(b[1]));
}
__device__ __forceinline__ void cp16(uint32_t sdst, const void* gsrc) {
    asm volatile("cp.async.cg.shared.global [%0], [%1], 16;" :: "r"(sdst), "l"(gsrc));
}
__device__ __forceinline__ void split2(float x, float y, uint32_t& hi, uint32_t& lo) {
    __nv_bfloat16 hx = __float2bfloat16(x), hy = __float2bfloat16(y);
    __nv_bfloat16 lx = __float2bfloat16(x - __bfloat162float(hx));
    __nv_bfloat16 ly = __float2bfloat16(y - __bfloat162float(hy));
    __nv_bfloat162 hp(hx, hy), lp(lx, ly);
    hi = *reinterpret_cast<uint32_t*>(&hp);
    lo = *reinterpret_cast<uint32_t*>(&lp);
}
__device__ __forceinline__ uint16_t split_pick(float w, int t) {
    __nv_bfloat16 hi = __float2bfloat16(w);
    if (t == 0) return *reinterpret_cast<uint16_t*>(&hi);
    __nv_bfloat16 lo = __float2bfloat16(w - __bfloat162float(hi));
    return *reinterpret_cast<uint16_t*>(&lo);
}

// ---------------------------------------------------------------------------
// k0: pack W2 (fp16), W1/W3 (bf16 hi/lo). Bounds-clean.
// ---------------------------------------------------------------------------
__global__ void k0_prep(const float* __restrict__ W1, const float* __restrict__ W2,
                        const float* __restrict__ W3)
{
    int i = blockIdx.x * 256 + threadIdx.x;
    if (i < 81920) {                                   // W2: [c][n][40] fp16
        int kl = i % 40, n = (i / 40) % 256, c = i / 10240;
        __half v = (kl < 32) ? __float2half_rn(W2[(c*32 + kl)*256 + n]) : __half(0.f);
        g_W2h[i] = *reinterpret_cast<uint16_t*>(&v);
    } else if (i < 81920 + 139264) {                   // W1: [hf][t][n][136]
        int j = i - 81920;
        int k = j % 136, n = (j / 136) % 256, t = (j / 34816) % 2, hf = j / 69632;
        g_W1p[j] = (k < 128) ? split_pick(W1[(hf*128 + k)*256 + n], t) : (uint16_t)0;
    } else if (i < 81920 + 139264 + 69632) {           // W3: [kc][t][n][136]
        int j = i - 221184;
        int k = j % 136, n = (j / 136) % 128, t = (j / 17408) % 2, kc = j / 34816;
        g_W3p[j] = (k < 128) ? split_pick(W3[(kc*128 + k)*128 + n], t) : (uint16_t)0;
    }
}

// ---------------------------------------------------------------------------
// k1 (HMMA bf16 3-term, R8-proven): grid (128, 2)
// ---------------------------------------------------------------------------
#define OFF1_W  0
#define OFF1_A  139264
#define OFF1_B1 208896
#define SMEM1   209920

__global__ __launch_bounds__(256, 1)
void k1_hmma(const float* __restrict__ feats, const float* __restrict__ b1)
{
    extern __shared__ char sm1[];
    uint16_t* sW   = (uint16_t*)(sm1 + OFF1_W);
    uint16_t* sAhi = (uint16_t*)(sm1 + OFF1_A);
    uint16_t* sAlo = sAhi + 128*136;
    float*    sb1  = (float*)(sm1 + OFF1_B1);
    uint32_t  swb  = smem_u32(sm1);

    int tid = threadIdx.x, lane = tid & 31, wid = tid >> 5;
    int wm = wid >> 2, wn = wid & 3, g4 = lane >> 2, l4 = lane & 3;
    int m0 = blockIdx.x * 128, hf = blockIdx.y;

    {
        const char* src = (const char*)(g_W1p + hf*69632) + tid*16;
        uint32_t dst = swb + OFF1_W + tid*16;
        #pragma unroll
        for (int it = 0; it < 34; ++it) cp16(dst + it*4096, src + it*4096);
        asm volatile("cp.async.commit_group;" ::: "memory");
    }
    sb1[tid] = (hf == 0) ? b1[tid] : 0.f;

    {
        int r = tid >> 1, kb = (tid & 1) * 64;
        const float* fr = feats + (size_t)(m0 + r)*CIN + kb;
        uint16_t* ph = sAhi + r*136 + kb;
        uint16_t* pl = sAlo + r*136 + kb;
        #pragma unroll
        for (int j = 0; j < 16; ++j) {
            float4 v = *(const float4*)(fr + 4*j);
            uint32_t h01, l01, h23, l23;
            split2(v.x, v.y, h01, l01);
            split2(v.z, v.w, h23, l23);
            *(uint32_t*)(ph + 4*j)     = h01;
            *(uint32_t*)(ph + 4*j + 2) = h23;
            *(uint32_t*)(pl + 4*j)     = l01;
            *(uint32_t*)(pl + 4*j + 2) = l23;
        }
    }
    asm volatile("cp.async.wait_group 0;" ::: "memory");
    __syncthreads();

    float acc[4][8][4];
    #pragma unroll
    for (int mi = 0; mi < 4; ++mi)
        #pragma unroll
        for (int ni = 0; ni < 8; ++ni)
            #pragma unroll
            for (int q = 0; q < 4; ++q) acc[mi][ni][q] = 0.f;

    const uint16_t* sWl = sW + 34816;
    #pragma unroll
    for (int ks = 0; ks < 8; ++ks) {
        int kk = ks*16 + l4*2;
        uint32_t ah[4][4], al[4][4], bb[8][2];
        #pragma unroll
        for (int mi = 0; mi < 4; ++mi) {
            const uint16_t* pa = sAhi + (wm*64 + mi*16 + g4)*136 + kk;
            ah[mi][0] = *(const uint32_t*)pa;
            ah[mi][1] = *(const uint32_t*)(pa + 8*136);
            ah[mi][2] = *(const uint32_t*)(pa + 8);
            ah[mi][3] = *(const uint32_t*)(pa + 8*136 + 8);
            const uint16_t* pb = sAlo + (wm*64 + mi*16 + g4)*136 + kk;
            al[mi][0] = *(const uint32_t*)pb;
            al[mi][1] = *(const uint32_t*)(pb + 8*136);
            al[mi][2] = *(const uint32_t*)(pb + 8);
            al[mi][3] = *(const uint32_t*)(pb + 8*136 + 8);
        }
        #pragma unroll
        for (int ni = 0; ni < 8; ++ni) {
            const uint16_t* p = sW + (wn*64 + ni*8 + g4)*136 + kk;
            bb[ni][0] = *(const uint32_t*)p;
            bb[ni][1] = *(const uint32_t*)(p + 8);
        }
        #pragma unroll
        for (int mi = 0; mi < 4; ++mi)
            #pragma unroll
            for (int ni = 0; ni < 8; ++ni) {
                mma_bf16(acc[mi][ni], ah[mi], bb[ni]);
                mma_bf16(acc[mi][ni], al[mi], bb[ni]);
            }
        #pragma unroll
        for (int ni = 0; ni < 8; ++ni) {
            const uint16_t* q = sWl + (wn*64 + ni*8 + g4)*136 + kk;
            bb[ni][0] = *(const uint32_t*)q;
            bb[ni][1] = *(const uint32_t*)(q + 8);
        }
        #pragma unroll
        for (int mi = 0; mi < 4; ++mi)
            #pragma unroll
            for (int ni = 0; ni < 8; ++ni)
                mma_bf16(acc[mi][ni], ah[mi], bb[ni]);
    }

    float* Out = hf ? g_Bm : g_A;
    #pragma unroll
    for (int mi = 0; mi < 4; ++mi) {
        int m = wm*64 + mi*16 + g4;
        #pragma unroll
        for (int ni = 0; ni < 8; ++ni) {
            int n0 = wn*64 + ni*8 + l4*2;
            float b0 = sb1[n0], bv1 = sb1[n0 + 1];
            *(float2*)(Out + (size_t)(m0 + m)*H + n0) =
                make_float2(acc[mi][ni][0] + b0, acc[mi][ni][1] + bv1);
            *(float2*)(Out + (size_t)(m0 + m + 8)*H + n0) =
                make_float2(acc[mi][ni][2] + b0, acc[mi][ni][3] + bv1);
        }
    }
}

// ---------------------------------------------------------------------------
// k2: edge MLP layer-2, PURE fp16 single-term HMMA. 2 CTAs/SM.
// ---------------------------------------------------------------------------
#define OFF_H1   0          // fp16 [128][264] = 67584
#define OFF_W2s  67584      // 2 stages x fp16[256][40] = 2 x 20480
#define OFF_B2   108544     // 256 floats
#define OFF_SIDX 109568
#define OFF_SVAL 110080
#define SMEM2    110592

__global__ __launch_bounds__(256, 2)
void k2_edge(const int* __restrict__ n_idxs, const int* __restrict__ nvalid,
             const float* __restrict__ b2)
{
    extern __shared__ char smem[];
    uint16_t* sh1  = (uint16_t*)(smem + OFF_H1);      // fp16 [128][264]
    float*    sb2  = (float*)(smem + OFF_B2);
    int*      sidx = (int*)(smem + OFF_SIDX);
    float*    sval = (float*)(smem + OFF_SVAL);
    uint32_t  swbase = smem_u32(smem) + OFF_W2s;

    int tid = threadIdx.x, lane = tid & 31, wid = tid >> 5;
    int wm = wid >> 2, wn = wid & 3;
    int node0 = blockIdx.x * 8;

    // prologue: stream W2 chunks 0,1 (20480B each = 5 x 16B/thread)
    #pragma unroll
    for (int s = 0; s < 2; ++s) {
        const char* src = (const char*)g_W2h + s*20480 + tid*16;
        uint32_t dst = swbase + s*20480 + tid*16;
        #pragma unroll
        for (int it = 0; it < 5; ++it)
            cp16(dst + it*4096, src + it*4096);
        asm volatile("cp.async.commit_group;" ::: "memory");
    }

    if (tid < 128) {
        sidx[tid] = n_idxs[node0*K_ + tid];
        sval[tid] = nvalid[node0*K_ + tid] ? 1.f : 0.f;
    }
    sb2[tid] = b2[tid];
    __syncthreads();

    // build h1 (fp16): thread -> row tid/2, col half (tid&1)*128
    {
        int e = tid >> 1, cb = (tid & 1) * 128;
        int node = node0 + (e >> 4);
        int gn = (node >> 12) * N_ + sidx[e];
        const float* ar = g_A  + (size_t)node * H + cb;
        const float* br = g_Bm + (size_t)gn   * H + cb;
        uint16_t* ph = sh1 + e*264 + cb;
        #pragma unroll
        for (int j = 0; j < 32; ++j) {
            float4 av = *(const float4*)(ar + 4*j);
            float4 bv = *(const float4*)(br + 4*j);
            __half2 p01 = __floats2half2_rn(fmaxf(av.x + bv.x, 0.f), fmaxf(av.y + bv.y, 0.f));
            __half2 p23 = __floats2half2_rn(fmaxf(av.z + bv.z, 0.f), fmaxf(av.w + bv.w, 0.f));
            *(uint32_t*)(ph + 4*j)     = *reinterpret_cast<uint32_t*>(&p01);
            *(uint32_t*)(ph + 4*j + 2) = *reinterpret_cast<uint32_t*>(&p23);
        }
    }

    float acc[4][8][4];
    #pragma unroll
    for (int mi = 0; mi < 4; ++mi)
        #pragma unroll
        for (int ni = 0; ni < 8; ++ni)
            #pragma unroll
            for (int q = 0; q < 4; ++q) acc[mi][ni][q] = 0.f;

    int g4 = lane >> 2, l4 = lane & 3;

    for (int c = 0; c < 8; ++c) {
        if (c == 7) asm volatile("cp.async.wait_group 0;" ::: "memory");
        else        asm volatile("cp.async.wait_group 1;" ::: "memory");
        __syncthreads();

        const uint16_t* sWc = (const uint16_t*)(smem + OFF_W2s + (c & 1)*20480);

        #pragma unroll
        for (int ks = 0; ks < 2; ++ks) {
            int kk = c*32 + ks*16 + l4*2;
            uint32_t ah[4][4], bb[8][2];
            #pragma unroll
            for (int mi = 0; mi < 4; ++mi) {
                const uint16_t* pa = sh1 + (wm*64 + mi*16 + g4)*264 + kk;
                ah[mi][0] = *(const uint32_t*)pa;
                ah[mi][1] = *(const uint32_t*)(pa + 8*264);
                ah[mi][2] = *(const uint32_t*)(pa + 8);
                ah[mi][3] = *(const uint32_t*)(pa + 8*264 + 8);
            }
            #pragma unroll
            for (int ni = 0; ni < 8; ++ni) {
                const uint16_t* p = sWc + (wn*64 + ni*8 + g4)*40 + ks*16 + l4*2;
                bb[ni][0] = *(const uint32_t*)p;
                bb[ni][1] = *(const uint32_t*)(p + 8);
            }
            #pragma unroll
            for (int mi = 0; mi < 4; ++mi)
                #pragma unroll
                for (int ni = 0; ni < 8; ++ni)
                    mma_f16(acc[mi][ni], ah[mi], bb[ni]);
        }
        __syncthreads();
        if (c < 6) {
            const char* src = (const char*)g_W2h + (c + 2)*20480 + tid*16;
            uint32_t dst = swbase + (c & 1)*20480 + tid*16;
            #pragma unroll
            for (int it = 0; it < 5; ++it)
                cp16(dst + it*4096, src + it*4096);
            asm volatile("cp.async.commit_group;" ::: "memory");
        }
    }

    // epilogue: bias + relu + mask, butterfly over 16 edges, store g_S
    #pragma unroll
    for (int mi = 0; mi < 4; ++mi) {
        int node_l = wm*4 + mi;
        float m1 = sval[node_l*16 + g4];
        float m2 = sval[node_l*16 + g4 + 8];
        int node_g = node0 + node_l;
        #pragma unroll
        for (int ni = 0; ni < 8; ++ni) {
            int n0 = wn*64 + ni*8 + l4*2;
            float s0 = fmaxf(acc[mi][ni][0] + sb2[n0],     0.f)*m1
                     + fmaxf(acc[mi][ni][2] + sb2[n0],     0.f)*m2;
            float s1 = fmaxf(acc[mi][ni][1] + sb2[n0 + 1], 0.f)*m1
                     + fmaxf(acc[mi][ni][3] + sb2[n0 + 1], 0.f)*m2;
            #pragma unroll
            for (int d = 4; d < 32; d <<= 1) {
                s0 += __shfl_xor_sync(0xFFFFFFFF, s0, d);
                s1 += __shfl_xor_sync(0xFFFFFFFF, s1, d);
            }
            if (g4 == 0)
                *(float2*)(g_S + (size_t)node_g*H + n0) = make_float2(s0, s1);
        }
    }
}

// ---------------------------------------------------------------------------
// k3 (HMMA bf16 3-term, R7-proven): grid 128
// ---------------------------------------------------------------------------
#define OFF3_A   0
#define OFF3_W   135168
#define OFF3_B3  204800
#define OFF3_CNT 205312
#define SMEM3    205824

__global__ __launch_bounds__(256, 1)
void k3_hmma(const int* __restrict__ nvalid, const float* __restrict__ b3,
             float* __restrict__ out)
{
    extern __shared__ char sm3[];
    uint16_t* sAhi = (uint16_t*)(sm3 + OFF3_A);
    uint16_t* sAlo = sAhi + 128*264;
    float*    sb3  = (float*)(sm3 + OFF3_B3);
    float*    scnt = (float*)(sm3 + OFF3_CNT);
    uint32_t  swb  = smem_u32(sm3);

    int tid = threadIdx.x, lane = tid & 31, wid = tid >> 5;
    int wm = wid >> 2, wn = wid & 3, g4 = lane >> 2, l4 = lane & 3;
    int m0 = blockIdx.x * 128;

    {
        const char* src = (const char*)g_W3p + tid*16;
        uint32_t dst = swb + OFF3_W + tid*16;
        #pragma unroll
        for (int it = 0; it < 17; ++it) cp16(dst + it*4096, src + it*4096);
        asm volatile("cp.async.commit_group;" ::: "memory");
    }
    if (tid < 128) {
        sb3[tid] = b3[tid];
        int c = 0;
        #pragma unroll
        for (int k = 0; k < K_; ++k) c += nvalid[(m0 + tid)*K_ + k];
        scnt[tid] = (float)c;
    }

    {
        int r = tid >> 1, kb = (tid & 1) * 128;
        const float* fr = g_S + (size_t)(m0 + r)*H + kb;
        uint16_t* ph = sAhi + r*264 + kb;
        uint16_t* pl = sAlo + r*264 + kb;
        #pragma unroll
        for (int j = 0; j < 32; ++j) {
            float4 v = *(const float4*)(fr + 4*j);
            uint32_t h01, l01, h23, l23;
            split2(v.x, v.y, h01, l01);
            split2(v.z, v.w, h23, l23);
            *(uint32_t*)(ph + 4*j)     = h01;
            *(uint32_t*)(ph + 4*j + 2) = h23;
            *(uint32_t*)(pl + 4*j)     = l01;
            *(uint32_t*)(pl + 4*j + 2) = l23;
        }
    }
    asm volatile("cp.async.wait_group 0;" ::: "memory");
    __syncthreads();

    float acc[4][4][4];
    #pragma unroll
    for (int mi = 0; mi < 4; ++mi)
        #pragma unroll
        for (int ni = 0; ni < 4; ++ni)
            #pragma unroll
            for (int q = 0; q < 4; ++q) acc[mi][ni][q] = 0.f;

    for (int kc = 0; kc < 2; ++kc) {
        const uint16_t* sW  = (const uint16_t*)(sm3 + OFF3_W);
        const uint16_t* sWl = sW + 17408;

        #pragma unroll
        for (int ks = 0; ks < 8; ++ks) {
            int kk = ks*16 + l4*2;
            int ka = kc*128 + kk;
            uint32_t ah[4][4], al[4][4], bb[4][2];
            #pragma unroll
            for (int mi = 0; mi < 4; ++mi) {
                const uint16_t* pa = sAhi + (wm*64 + mi*16 + g4)*264 + ka;
                ah[mi][0] = *(const uint32_t*)pa;
                ah[mi][1] = *(const uint32_t*)(pa + 8*264);
                ah[mi][2] = *(const uint32_t*)(pa + 8);
                ah[mi][3] = *(const uint32_t*)(pa + 8*264 + 8);
                const uint16_t* pb = sAlo + (wm*64 + mi*16 + g4)*264 + ka;
                al[mi][0] = *(const uint32_t*)pb;
                al[mi][1] = *(const uint32_t*)(pb + 8*264);
                al[mi][2] = *(const uint32_t*)(pb + 8);
                al[mi][3] = *(const uint32_t*)(pb + 8*264 + 8);
            }
            #pragma unroll
            for (int ni = 0; ni < 4; ++ni) {
                const uint16_t* p = sW + (wn*32 + ni*8 + g4)*136 + kk;
                bb[ni][0] = *(const uint32_t*)p;
                bb[ni][1] = *(const uint32_t*)(p + 8);
            }
            #pragma unroll
            for (int mi = 0; mi < 4; ++mi)
                #pragma unroll
                for (int ni = 0; ni < 4; ++ni) {
                    mma_bf16(acc[mi][ni], ah[mi], bb[ni]);
                    mma_bf16(acc[mi][ni], al[mi], bb[ni]);
                }
            #pragma unroll
            for (int ni = 0; ni < 4; ++ni) {
                const uint16_t* q = sWl + (wn*32 + ni*8 + g4)*136 + kk;
                bb[ni][0] = *(const uint32_t*)q;
                bb[ni][1] = *(const uint32_t*)(q + 8);
            }
            #pragma unroll
            for (int mi = 0; mi < 4; ++mi)
                #pragma unroll
                for (int ni = 0; ni < 4; ++ni)
                    mma_bf16(acc[mi][ni], ah[mi], bb[ni]);
        }
        __syncthreads();
        if (kc == 0) {
            const char* src = (const char*)g_W3p + 69632 + tid*16;
            uint32_t dst = swb + OFF3_W + tid*16;
            #pragma unroll
            for (int it = 0; it < 17; ++it) cp16(dst + it*4096, src + it*4096);
            asm volatile("cp.async.commit_group;" ::: "memory");
            asm volatile("cp.async.wait_group 0;" ::: "memory");
            __syncthreads();
        }
    }

    #pragma unroll
    for (int mi = 0; mi < 4; ++mi) {
        int m = wm*64 + mi*16 + g4;
        #pragma unroll
        for (int ni = 0; ni < 4; ++ni) {
            int n0 = wn*32 + ni*8 + l4*2;
            float b0 = sb3[n0], bv1 = sb3[n0 + 1];
            *(float2*)(out + (size_t)(m0 + m)*COUT + n0) =
                make_float2(acc[mi][ni][0] + b0*scnt[m], acc[mi][ni][1] + bv1*scnt[m]);
            *(float2*)(out + (size_t)(m0 + m + 8)*COUT + n0) =
                make_float2(acc[mi][ni][2] + b0*scnt[m + 8], acc[mi][ni][3] + bv1*scnt[m + 8]);
        }
    }
}

// ---------------------------------------------------------------------------
extern "C" void kernel_launch(void* const* d_in, const int* in_sizes, int n_in,
                              void* d_out, int out_size)
{
    const float* feats  = (const float*)d_in[2];
    const int*   n_idxs = (const int*)  d_in[3];
    const int*   nvalid = (const int*)  d_in[4];
    const float* W1     = (const float*)d_in[5];
    const float* b1     = (const float*)d_in[6];
    const float* W2     = (const float*)d_in[7];
    const float* b2     = (const float*)d_in[8];
    const float* W3     = (const float*)d_in[9];
    const float* b3     = (const float*)d_in[10];
    float* out = (float*)d_out;

    cudaFuncSetAttribute(k1_hmma, cudaFuncAttributeMaxDynamicSharedMemorySize, SMEM1);
    cudaFuncSetAttribute(k2_edge, cudaFuncAttributeMaxDynamicSharedMemorySize, SMEM2);
    cudaFuncSetAttribute(k3_hmma, cudaFuncAttributeMaxDynamicSharedMemorySize, SMEM3);

    k0_prep<<<1136, 256>>>(W1, W2, W3);
    k1_hmma<<<dim3(128, 2), 256, SMEM1>>>(feats, b1);
    k2_edge<<<NODES/8, 256, SMEM2>>>(n_idxs, nvalid, b2);
    k3_hmma<<<128, 256, SMEM3>>>(nvalid, b3, out);
}

// round 10
// speedup vs baseline: 3.0258x; 1.2792x over previous
#include <cuda_runtime.h>
#include <cuda_bf16.h>
#include <cuda_fp16.h>
#include <cstdint>

#define B_    4
#define N_    4096
#define K_    16
#define CIN   128
#define H     256
#define COUT  128
#define NODES (B_*N_)

__device__ float g_A [NODES*H];   // feats @ W1[:128,:] + b1
__device__ float g_Bm[NODES*H];   // feats @ W1[128:,:]
__device__ float g_S [NODES*H];   // sum_k mask*h2
// W1 split/packed bf16: [hf:2][t:2][n:256][k:136]
__device__ __align__(16) uint16_t g_W1p[2*2*256*136];
// W2 packed fp16 (single precision term): [chunk c:8][n:256][k:40]
__device__ __align__(16) uint16_t g_W2h[8*256*40];
// W3 split/packed bf16: [kc:2][t:2][n:128][k:136]
__device__ __align__(16) uint16_t g_W3p[2*2*128*136];

// ---------------- helpers ----------------
__device__ __forceinline__ uint32_t smem_u32(const void* p) {
    uint32_t a;
    asm("{ .reg .u64 t; cvta.to.shared.u64 t, %1; cvt.u32.u64 %0, t; }" : "=r"(a) : "l"(p));
    return a;
}
__device__ __forceinline__ void mma_bf16(float* d, const uint32_t* a, const uint32_t* b) {
    asm volatile("mma.sync.aligned.m16n8k16.row.col.f32.bf16.bf16.f32 "
        "{%0,%1,%2,%3}, {%4,%5,%6,%7}, {%8,%9}, {%0,%1,%2,%3};"
        : "+f"(d[0]), "+f"(d[1]), "+f"(d[2]), "+f"(d[3])
        : "r"(a[0]), "r"(a[1]), "r"(a[2]), "r"(a[3]), "r"(b[0]), "r"(b[1]));
}
__device__ __forceinline__ void mma_f16(float* d, const uint32_t* a, const uint32_t* b) {
    asm volatile("mma.sync.aligned.m16n8k16.row.col.f32.f16.f16.f32 "
        "{%0,%1,%2,%3}, {%4,%5,%6,%7}, {%8,%9}, {%0,%1,%2,%3};"
        : "+f"(d[0]), "+f"(d[1]), "+f"(d[2]), "+f"(d[3])
        : "r"(a[0]), "r"(a[1]), "r"(a[2]), "r"(a[3]), "r"(b[0]), "r"(b[1]));
}
__device__ __forceinline__ void cp16(uint32_t sdst, const void* gsrc) {
    asm volatile("cp.async.cg.shared.global [%0], [%1], 16;" :: "r"(sdst), "l"(gsrc));
}
__device__ __forceinline__ void split2(float x, float y, uint32_t& hi, uint32_t& lo) {
    __nv_bfloat16 hx = __float2bfloat16(x), hy = __float2bfloat16(y);
    __nv_bfloat16 lx = __float2bfloat16(x - __bfloat162float(hx));
    __nv_bfloat16 ly = __float2bfloat16(y - __bfloat162float(hy));
    __nv_bfloat162 hp(hx, hy), lp(lx, ly);
    hi = *reinterpret_cast<uint32_t*>(&hp);
    lo = *reinterpret_cast<uint32_t*>(&lp);
}
__device__ __forceinline__ uint16_t split_pick(float w, int t) {
    __nv_bfloat16 hi = __float2bfloat16(w);
    if (t == 0) return *reinterpret_cast<uint16_t*>(&hi);
    __nv_bfloat16 lo = __float2bfloat16(w - __bfloat162float(hi));
    return *reinterpret_cast<uint16_t*>(&lo);
}
__device__ __forceinline__ uint32_t pack_h2(float x, float y) {
    __half2 p = __floats2half2_rn(x, y);
    return *reinterpret_cast<uint32_t*>(&p);
}

// ---------------------------------------------------------------------------
// k0: pack W2 (fp16), W1/W3 (bf16 hi/lo). Bounds-clean.
// ---------------------------------------------------------------------------
__global__ void k0_prep(const float* __restrict__ W1, const float* __restrict__ W2,
                        const float* __restrict__ W3)
{
    int i = blockIdx.x * 256 + threadIdx.x;
    if (i < 81920) {                                   // W2: [c][n][40] fp16
        int kl = i % 40, n = (i / 40) % 256, c = i / 10240;
        __half v = (kl < 32) ? __float2half_rn(W2[(c*32 + kl)*256 + n]) : __half(0.f);
        g_W2h[i] = *reinterpret_cast<uint16_t*>(&v);
    } else if (i < 81920 + 139264) {                   // W1: [hf][t][n][136]
        int j = i - 81920;
        int k = j % 136, n = (j / 136) % 256, t = (j / 34816) % 2, hf = j / 69632;
        g_W1p[j] = (k < 128) ? split_pick(W1[(hf*128 + k)*256 + n], t) : (uint16_t)0;
    } else if (i < 81920 + 139264 + 69632) {           // W3: [kc][t][n][136]
        int j = i - 221184;
        int k = j % 136, n = (j / 136) % 128, t = (j / 17408) % 2, kc = j / 34816;
        g_W3p[j] = (k < 128) ? split_pick(W3[(kc*128 + k)*128 + n], t) : (uint16_t)0;
    }
}

// ---------------------------------------------------------------------------
// k1 (HMMA bf16 3-term, R8-proven): grid (128, 2)
// ---------------------------------------------------------------------------
#define OFF1_W  0
#define OFF1_A  139264
#define OFF1_B1 208896
#define SMEM1   209920

__global__ __launch_bounds__(256, 1)
void k1_hmma(const float* __restrict__ feats, const float* __restrict__ b1)
{
    extern __shared__ char sm1[];
    uint16_t* sW   = (uint16_t*)(sm1 + OFF1_W);
    uint16_t* sAhi = (uint16_t*)(sm1 + OFF1_A);
    uint16_t* sAlo = sAhi + 128*136;
    float*    sb1  = (float*)(sm1 + OFF1_B1);
    uint32_t  swb  = smem_u32(sm1);

    int tid = threadIdx.x, lane = tid & 31, wid = tid >> 5;
    int wm = wid >> 2, wn = wid & 3, g4 = lane >> 2, l4 = lane & 3;
    int m0 = blockIdx.x * 128, hf = blockIdx.y;

    {
        const char* src = (const char*)(g_W1p + hf*69632) + tid*16;
        uint32_t dst = swb + OFF1_W + tid*16;
        #pragma unroll
        for (int it = 0; it < 34; ++it) cp16(dst + it*4096, src + it*4096);
        asm volatile("cp.async.commit_group;" ::: "memory");
    }
    sb1[tid] = (hf == 0) ? b1[tid] : 0.f;

    {
        int r = tid >> 1, kb = (tid & 1) * 64;
        const float* fr = feats + (size_t)(m0 + r)*CIN + kb;
        uint16_t* ph = sAhi + r*136 + kb;
        uint16_t* pl = sAlo + r*136 + kb;
        #pragma unroll
        for (int j = 0; j < 16; ++j) {
            float4 v = *(const float4*)(fr + 4*j);
            uint32_t h01, l01, h23, l23;
            split2(v.x, v.y, h01, l01);
            split2(v.z, v.w, h23, l23);
            *(uint32_t*)(ph + 4*j)     = h01;
            *(uint32_t*)(ph + 4*j + 2) = h23;
            *(uint32_t*)(pl + 4*j)     = l01;
            *(uint32_t*)(pl + 4*j + 2) = l23;
        }
    }
    asm volatile("cp.async.wait_group 0;" ::: "memory");
    __syncthreads();

    float acc[4][8][4];
    #pragma unroll
    for (int mi = 0; mi < 4; ++mi)
        #pragma unroll
        for (int ni = 0; ni < 8; ++ni)
            #pragma unroll
            for (int q = 0; q < 4; ++q) acc[mi][ni][q] = 0.f;

    const uint16_t* sWl = sW + 34816;
    #pragma unroll
    for (int ks = 0; ks < 8; ++ks) {
        int kk = ks*16 + l4*2;
        uint32_t ah[4][4], al[4][4], bb[8][2];
        #pragma unroll
        for (int mi = 0; mi < 4; ++mi) {
            const uint16_t* pa = sAhi + (wm*64 + mi*16 + g4)*136 + kk;
            ah[mi][0] = *(const uint32_t*)pa;
            ah[mi][1] = *(const uint32_t*)(pa + 8*136);
            ah[mi][2] = *(const uint32_t*)(pa + 8);
            ah[mi][3] = *(const uint32_t*)(pa + 8*136 + 8);
            const uint16_t* pb = sAlo + (wm*64 + mi*16 + g4)*136 + kk;
            al[mi][0] = *(const uint32_t*)pb;
            al[mi][1] = *(const uint32_t*)(pb + 8*136);
            al[mi][2] = *(const uint32_t*)(pb + 8);
            al[mi][3] = *(const uint32_t*)(pb + 8*136 + 8);
        }
        #pragma unroll
        for (int ni = 0; ni < 8; ++ni) {
            const uint16_t* p = sW + (wn*64 + ni*8 + g4)*136 + kk;
            bb[ni][0] = *(const uint32_t*)p;
            bb[ni][1] = *(const uint32_t*)(p + 8);
        }
        #pragma unroll
        for (int mi = 0; mi < 4; ++mi)
            #pragma unroll
            for (int ni = 0; ni < 8; ++ni) {
                mma_bf16(acc[mi][ni], ah[mi], bb[ni]);
                mma_bf16(acc[mi][ni], al[mi], bb[ni]);
            }
        #pragma unroll
        for (int ni = 0; ni < 8; ++ni) {
            const uint16_t* q = sWl + (wn*64 + ni*8 + g4)*136 + kk;
            bb[ni][0] = *(const uint32_t*)q;
            bb[ni][1] = *(const uint32_t*)(q + 8);
        }
        #pragma unroll
        for (int mi = 0; mi < 4; ++mi)
            #pragma unroll
            for (int ni = 0; ni < 8; ++ni)
                mma_bf16(acc[mi][ni], ah[mi], bb[ni]);
    }

    float* Out = hf ? g_Bm : g_A;
    #pragma unroll
    for (int mi = 0; mi < 4; ++mi) {
        int m = wm*64 + mi*16 + g4;
        #pragma unroll
        for (int ni = 0; ni < 8; ++ni) {
            int n0 = wn*64 + ni*8 + l4*2;
            float b0 = sb1[n0], bv1 = sb1[n0 + 1];
            *(float2*)(Out + (size_t)(m0 + m)*H + n0) =
                make_float2(acc[mi][ni][0] + b0, acc[mi][ni][1] + bv1);
            *(float2*)(Out + (size_t)(m0 + m + 8)*H + n0) =
                make_float2(acc[mi][ni][2] + b0, acc[mi][ni][3] + bv1);
        }
    }
}

// ---------------------------------------------------------------------------
// k2: edge MLP layer-2, fp16 single-term HMMA, COALESCED warp-per-node gather.
// ---------------------------------------------------------------------------
#define OFF_H1   0          // fp16 [128][264] = 67584
#define OFF_W2s  67584      // 2 stages x fp16[256][40] = 2 x 20480
#define OFF_B2   108544     // 256 floats
#define OFF_SIDX 109568
#define OFF_SVAL 110080
#define SMEM2    110592

__global__ __launch_bounds__(256, 2)
void k2_edge(const int* __restrict__ n_idxs, const int* __restrict__ nvalid,
             const float* __restrict__ b2)
{
    extern __shared__ char smem[];
    uint16_t* sh1  = (uint16_t*)(smem + OFF_H1);      // fp16 [128][264]
    float*    sb2  = (float*)(smem + OFF_B2);
    int*      sidx = (int*)(smem + OFF_SIDX);
    float*    sval = (float*)(smem + OFF_SVAL);
    uint32_t  swbase = smem_u32(smem) + OFF_W2s;

    int tid = threadIdx.x, lane = tid & 31, wid = tid >> 5;
    int wm = wid >> 2, wn = wid & 3;
    int node0 = blockIdx.x * 8;

    // prologue: stream W2 chunks 0,1 (20480B each = 5 x 16B/thread)
    #pragma unroll
    for (int s = 0; s < 2; ++s) {
        const char* src = (const char*)g_W2h + s*20480 + tid*16;
        uint32_t dst = swbase + s*20480 + tid*16;
        #pragma unroll
        for (int it = 0; it < 5; ++it)
            cp16(dst + it*4096, src + it*4096);
        asm volatile("cp.async.commit_group;" ::: "memory");
    }

    if (tid < 128) {
        sidx[tid] = n_idxs[node0*K_ + tid];
        sval[tid] = nvalid[node0*K_ + tid] ? 1.f : 0.f;
    }
    sb2[tid] = b2[tid];
    __syncthreads();

    // build h1 (fp16): warp w owns node node0+w; 16 edges, fully coalesced.
    // lane covers cols [4*lane,4*lane+4) and [128+4*lane, +4).
    {
        int node = node0 + wid;
        int boff = (node >> 12) * N_;
        const float* arow = g_A + (size_t)node * H;
        float4 a0 = *(const float4*)(arow + 4*lane);
        float4 a1 = *(const float4*)(arow + 128 + 4*lane);
        #pragma unroll 4
        for (int i = 0; i < 16; ++i) {
            int e = wid*16 + i;
            const float* brow = g_Bm + (size_t)(boff + sidx[e]) * H;
            float4 v0 = *(const float4*)(brow + 4*lane);
            float4 v1 = *(const float4*)(brow + 128 + 4*lane);
            uint2 w0, w1;
            w0.x = pack_h2(fmaxf(a0.x + v0.x, 0.f), fmaxf(a0.y + v0.y, 0.f));
            w0.y = pack_h2(fmaxf(a0.z + v0.z, 0.f), fmaxf(a0.w + v0.w, 0.f));
            w1.x = pack_h2(fmaxf(a1.x + v1.x, 0.f), fmaxf(a1.y + v1.y, 0.f));
            w1.y = pack_h2(fmaxf(a1.z + v1.z, 0.f), fmaxf(a1.w + v1.w, 0.f));
            uint16_t* ph = sh1 + e*264;
            *(uint2*)(ph + 4*lane)       = w0;
            *(uint2*)(ph + 128 + 4*lane) = w1;
        }
    }

    float acc[4][8][4];
    #pragma unroll
    for (int mi = 0; mi < 4; ++mi)
        #pragma unroll
        for (int ni = 0; ni < 8; ++ni)
            #pragma unroll
            for (int q = 0; q < 4; ++q) acc[mi][ni][q] = 0.f;

    int g4 = lane >> 2, l4 = lane & 3;

    for (int c = 0; c < 8; ++c) {
        if (c == 7) asm volatile("cp.async.wait_group 0;" ::: "memory");
        else        asm volatile("cp.async.wait_group 1;" ::: "memory");
        __syncthreads();

        const uint16_t* sWc = (const uint16_t*)(smem + OFF_W2s + (c & 1)*20480);

        #pragma unroll
        for (int ks = 0; ks < 2; ++ks) {
            int kk = c*32 + ks*16 + l4*2;
            uint32_t ah[4][4], bb[8][2];
            #pragma unroll
            for (int mi = 0; mi < 4; ++mi) {
                const uint16_t* pa = sh1 + (wm*64 + mi*16 + g4)*264 + kk;
                ah[mi][0] = *(const uint32_t*)pa;
                ah[mi][1] = *(const uint32_t*)(pa + 8*264);
                ah[mi][2] = *(const uint32_t*)(pa + 8);
                ah[mi][3] = *(const uint32_t*)(pa + 8*264 + 8);
            }
            #pragma unroll
            for (int ni = 0; ni < 8; ++ni) {
                const uint16_t* p = sWc + (wn*64 + ni*8 + g4)*40 + ks*16 + l4*2;
                bb[ni][0] = *(const uint32_t*)p;
                bb[ni][1] = *(const uint32_t*)(p + 8);
            }
            #pragma unroll
            for (int mi = 0; mi < 4; ++mi)
                #pragma unroll
                for (int ni = 0; ni < 8; ++ni)
                    mma_f16(acc[mi][ni], ah[mi], bb[ni]);
        }
        __syncthreads();
        if (c < 6) {
            const char* src = (const char*)g_W2h + (c + 2)*20480 + tid*16;
            uint32_t dst = swbase + (c & 1)*20480 + tid*16;
            #pragma unroll
            for (int it = 0; it < 5; ++it)
                cp16(dst + it*4096, src + it*4096);
            asm volatile("cp.async.commit_group;" ::: "memory");
        }
    }

    // epilogue: bias + relu + mask, butterfly over 16 edges, store g_S
    #pragma unroll
    for (int mi = 0; mi < 4; ++mi) {
        int node_l = wm*4 + mi;
        float m1 = sval[node_l*16 + g4];
        float m2 = sval[node_l*16 + g4 + 8];
        int node_g = node0 + node_l;
        #pragma unroll
        for (int ni = 0; ni < 8; ++ni) {
            int n0 = wn*64 + ni*8 + l4*2;
            float s0 = fmaxf(acc[mi][ni][0] + sb2[n0],     0.f)*m1
                     + fmaxf(acc[mi][ni][2] + sb2[n0],     0.f)*m2;
            float s1 = fmaxf(acc[mi][ni][1] + sb2[n0 + 1], 0.f)*m1
                     + fmaxf(acc[mi][ni][3] + sb2[n0 + 1], 0.f)*m2;
            #pragma unroll
            for (int d = 4; d < 32; d <<= 1) {
                s0 += __shfl_xor_sync(0xFFFFFFFF, s0, d);
                s1 += __shfl_xor_sync(0xFFFFFFFF, s1, d);
            }
            if (g4 == 0)
                *(float2*)(g_S + (size_t)node_g*H + n0) = make_float2(s0, s1);
        }
    }
}

// ---------------------------------------------------------------------------
// k3 (HMMA bf16 3-term, R7-proven): grid 128
// ---------------------------------------------------------------------------
#define OFF3_A   0
#define OFF3_W   135168
#define OFF3_B3  204800
#define OFF3_CNT 205312
#define SMEM3    205824

__global__ __launch_bounds__(256, 1)
void k3_hmma(const int* __restrict__ nvalid, const float* __restrict__ b3,
             float* __restrict__ out)
{
    extern __shared__ char sm3[];
    uint16_t* sAhi = (uint16_t*)(sm3 + OFF3_A);
    uint16_t* sAlo = sAhi + 128*264;
    float*    sb3  = (float*)(sm3 + OFF3_B3);
    float*    scnt = (float*)(sm3 + OFF3_CNT);
    uint32_t  swb  = smem_u32(sm3);

    int tid = threadIdx.x, lane = tid & 31, wid = tid >> 5;
    int wm = wid >> 2, wn = wid & 3, g4 = lane >> 2, l4 = lane & 3;
    int m0 = blockIdx.x * 128;

    {
        const char* src = (const char*)g_W3p + tid*16;
        uint32_t dst = swb + OFF3_W + tid*16;
        #pragma unroll
        for (int it = 0; it < 17; ++it) cp16(dst + it*4096, src + it*4096);
        asm volatile("cp.async.commit_group;" ::: "memory");
    }
    if (tid < 128) {
        sb3[tid] = b3[tid];
        int c = 0;
        #pragma unroll
        for (int k = 0; k < K_; ++k) c += nvalid[(m0 + tid)*K_ + k];
        scnt[tid] = (float)c;
    }

    {
        int r = tid >> 1, kb = (tid & 1) * 128;
        const float* fr = g_S + (size_t)(m0 + r)*H + kb;
        uint16_t* ph = sAhi + r*264 + kb;
        uint16_t* pl = sAlo + r*264 + kb;
        #pragma unroll
        for (int j = 0; j < 32; ++j) {
            float4 v = *(const float4*)(fr + 4*j);
            uint32_t h01, l01, h23, l23;
            split2(v.x, v.y, h01, l01);
            split2(v.z, v.w, h23, l23);
            *(uint32_t*)(ph + 4*j)     = h01;
            *(uint32_t*)(ph + 4*j + 2) = h23;
            *(uint32_t*)(pl + 4*j)     = l01;
            *(uint32_t*)(pl + 4*j + 2) = l23;
        }
    }
    asm volatile("cp.async.wait_group 0;" ::: "memory");
    __syncthreads();

    float acc[4][4][4];
    #pragma unroll
    for (int mi = 0; mi < 4; ++mi)
        #pragma unroll
        for (int ni = 0; ni < 4; ++ni)
            #pragma unroll
            for (int q = 0; q < 4; ++q) acc[mi][ni][q] = 0.f;

    for (int kc = 0; kc < 2; ++kc) {
        const uint16_t* sW  = (const uint16_t*)(sm3 + OFF3_W);
        const uint16_t* sWl = sW + 17408;

        #pragma unroll
        for (int ks = 0; ks < 8; ++ks) {
            int kk = ks*16 + l4*2;
            int ka = kc*128 + kk;
            uint32_t ah[4][4], al[4][4], bb[4][2];
            #pragma unroll
            for (int mi = 0; mi < 4; ++mi) {
                const uint16_t* pa = sAhi + (wm*64 + mi*16 + g4)*264 + ka;
                ah[mi][0] = *(const uint32_t*)pa;
                ah[mi][1] = *(const uint32_t*)(pa + 8*264);
                ah[mi][2] = *(const uint32_t*)(pa + 8);
                ah[mi][3] = *(const uint32_t*)(pa + 8*264 + 8);
                const uint16_t* pb = sAlo + (wm*64 + mi*16 + g4)*264 + ka;
                al[mi][0] = *(const uint32_t*)pb;
                al[mi][1] = *(const uint32_t*)(pb + 8*264);
                al[mi][2] = *(const uint32_t*)(pb + 8);
                al[mi][3] = *(const uint32_t*)(pb + 8*264 + 8);
            }
            #pragma unroll
            for (int ni = 0; ni < 4; ++ni) {
                const uint16_t* p = sW + (wn*32 + ni*8 + g4)*136 + kk;
                bb[ni][0] = *(const uint32_t*)p;
                bb[ni][1] = *(const uint32_t*)(p + 8);
            }
            #pragma unroll
            for (int mi = 0; mi < 4; ++mi)
                #pragma unroll
                for (int ni = 0; ni < 4; ++ni) {
                    mma_bf16(acc[mi][ni], ah[mi], bb[ni]);
                    mma_bf16(acc[mi][ni], al[mi], bb[ni]);
                }
            #pragma unroll
            for (int ni = 0; ni < 4; ++ni) {
                const uint16_t* q = sWl + (wn*32 + ni*8 + g4)*136 + kk;
                bb[ni][0] = *(const uint32_t*)q;
                bb[ni][1] = *(const uint32_t*)(q + 8);
            }
            #pragma unroll
            for (int mi = 0; mi < 4; ++mi)
                #pragma unroll
                for (int ni = 0; ni < 4; ++ni)
                    mma_bf16(acc[mi][ni], ah[mi], bb[ni]);
        }
        __syncthreads();
        if (kc == 0) {
            const char* src = (const char*)g_W3p + 69632 + tid*16;
            uint32_t dst = swb + OFF3_W + tid*16;
            #pragma unroll
            for (int it = 0; it < 17; ++it) cp16(dst + it*4096, src + it*4096);
            asm volatile("cp.async.commit_group;" ::: "memory");
            asm volatile("cp.async.wait_group 0;" ::: "memory");
            __syncthreads();
        }
    }

    #pragma unroll
    for (int mi = 0; mi < 4; ++mi) {
        int m = wm*64 + mi*16 + g4;
        #pragma unroll
        for (int ni = 0; ni < 4; ++ni) {
            int n0 = wn*32 + ni*8 + l4*2;
            float b0 = sb3[n0], bv1 = sb3[n0 + 1];
            *(float2*)(out + (size_t)(m0 + m)*COUT + n0) =
                make_float2(acc[mi][ni][0] + b0*scnt[m], acc[mi][ni][1] + bv1*scnt[m]);
            *(float2*)(out + (size_t)(m0 + m + 8)*COUT + n0) =
                make_float2(acc[mi][ni][2] + b0*scnt[m + 8], acc[mi][ni][3] + bv1*scnt[m + 8]);
        }
    }
}

// ---------------------------------------------------------------------------
extern "C" void kernel_launch(void* const* d_in, const int* in_sizes, int n_in,
                              void* d_out, int out_size)
{
    const float* feats  = (const float*)d_in[2];
    const int*   n_idxs = (const int*)  d_in[3];
    const int*   nvalid = (const int*)  d_in[4];
    const float* W1     = (const float*)d_in[5];
    const float* b1     = (const float*)d_in[6];
    const float* W2     = (const float*)d_in[7];
    const float* b2     = (const float*)d_in[8];
    const float* W3     = (const float*)d_in[9];
    const float* b3     = (const float*)d_in[10];
    float* out = (float*)d_out;

    cudaFuncSetAttribute(k1_hmma, cudaFuncAttributeMaxDynamicSharedMemorySize, SMEM1);
    cudaFuncSetAttribute(k2_edge, cudaFuncAttributeMaxDynamicSharedMemorySize, SMEM2);
    cudaFuncSetAttribute(k3_hmma, cudaFuncAttributeMaxDynamicSharedMemorySize, SMEM3);

    k0_prep<<<1136, 256>>>(W1, W2, W3);
    k1_hmma<<<dim3(128, 2), 256, SMEM1>>>(feats, b1);
    k2_edge<<<NODES/8, 256, SMEM2>>>(n_idxs, nvalid, b2);
    k3_hmma<<<128, 256, SMEM3>>>(nvalid, b3, out);
}

// round 11
// speedup vs baseline: 4.5367x; 1.4993x over previous
#include <cuda_runtime.h>
#include <cuda_bf16.h>
#include <cuda_fp16.h>
#include <cstdint>

#define B_    4
#define N_    4096
#define K_    16
#define CIN   128
#define H     256
#define COUT  128
#define NODES (B_*N_)

__device__ float g_A [NODES*H];   // feats @ W1[:128,:] + b1
__device__ float g_Bm[NODES*H];   // feats @ W1[128:,:]
__device__ float g_S [NODES*H];   // sum_k mask*h2
// W1 split/packed bf16: [hf:2][t:2][n:256][k:136]
__device__ __align__(16) uint16_t g_W1p[2*2*256*136];
// W2 packed fp16 (single precision term): [chunk c:8][n:256][k:40]
__device__ __align__(16) uint16_t g_W2h[8*256*40];
// W3 split/packed bf16: [kc:2][t:2][n:128][k:136]
__device__ __align__(16) uint16_t g_W3p[2*2*128*136];

// ---------------- helpers ----------------
__device__ __forceinline__ uint32_t smem_u32(const void* p) {
    uint32_t a;
    asm("{ .reg .u64 t; cvta.to.shared.u64 t, %1; cvt.u32.u64 %0, t; }" : "=r"(a) : "l"(p));
    return a;
}
__device__ __forceinline__ void mma_bf16(float* d, const uint32_t* a, const uint32_t* b) {
    asm volatile("mma.sync.aligned.m16n8k16.row.col.f32.bf16.bf16.f32 "
        "{%0,%1,%2,%3}, {%4,%5,%6,%7}, {%8,%9}, {%0,%1,%2,%3};"
        : "+f"(d[0]), "+f"(d[1]), "+f"(d[2]), "+f"(d[3])
        : "r"(a[0]), "r"(a[1]), "r"(a[2]), "r"(a[3]), "r"(b[0]), "r"(b[1]));
}
__device__ __forceinline__ void mma_f16(float* d, const uint32_t* a, const uint32_t* b) {
    asm volatile("mma.sync.aligned.m16n8k16.row.col.f32.f16.f16.f32 "
        "{%0,%1,%2,%3}, {%4,%5,%6,%7}, {%8,%9}, {%0,%1,%2,%3};"
        : "+f"(d[0]), "+f"(d[1]), "+f"(d[2]), "+f"(d[3])
        : "r"(a[0]), "r"(a[1]), "r"(a[2]), "r"(a[3]), "r"(b[0]), "r"(b[1]));
}
__device__ __forceinline__ void cp16(uint32_t sdst, const void* gsrc) {
    asm volatile("cp.async.cg.shared.global [%0], [%1], 16;" :: "r"(sdst), "l"(gsrc));
}
__device__ __forceinline__ void split2(float x, float y, uint32_t& hi, uint32_t& lo) {
    __nv_bfloat16 hx = __float2bfloat16(x), hy = __float2bfloat16(y);
    __nv_bfloat16 lx = __float2bfloat16(x - __bfloat162float(hx));
    __nv_bfloat16 ly = __float2bfloat16(y - __bfloat162float(hy));
    __nv_bfloat162 hp(hx, hy), lp(lx, ly);
    hi = *reinterpret_cast<uint32_t*>(&hp);
    lo = *reinterpret_cast<uint32_t*>(&lp);
}
__device__ __forceinline__ uint16_t split_pick(float w, int t) {
    __nv_bfloat16 hi = __float2bfloat16(w);
    if (t == 0) return *reinterpret_cast<uint16_t*>(&hi);
    __nv_bfloat16 lo = __float2bfloat16(w - __bfloat162float(hi));
    return *reinterpret_cast<uint16_t*>(&lo);
}
__device__ __forceinline__ uint32_t pack_h2(float x, float y) {
    __half2 p = __floats2half2_rn(x, y);
    return *reinterpret_cast<uint32_t*>(&p);
}

// ---------------------------------------------------------------------------
// k0: pack W2 (fp16), W1/W3 (bf16 hi/lo). Bounds-clean.
// ---------------------------------------------------------------------------
__global__ void k0_prep(const float* __restrict__ W1, const float* __restrict__ W2,
                        const float* __restrict__ W3)
{
    int i = blockIdx.x * 256 + threadIdx.x;
    if (i < 81920) {                                   // W2: [c][n][40] fp16
        int kl = i % 40, n = (i / 40) % 256, c = i / 10240;
        __half v = (kl < 32) ? __float2half_rn(W2[(c*32 + kl)*256 + n]) : __half(0.f);
        g_W2h[i] = *reinterpret_cast<uint16_t*>(&v);
    } else if (i < 81920 + 139264) {                   // W1: [hf][t][n][136]
        int j = i - 81920;
        int k = j % 136, n = (j / 136) % 256, t = (j / 34816) % 2, hf = j / 69632;
        g_W1p[j] = (k < 128) ? split_pick(W1[(hf*128 + k)*256 + n], t) : (uint16_t)0;
    } else if (i < 81920 + 139264 + 69632) {           // W3: [kc][t][n][136]
        int j = i - 221184;
        int k = j % 136, n = (j / 136) % 128, t = (j / 17408) % 2, kc = j / 34816;
        g_W3p[j] = (k < 128) ? split_pick(W3[(kc*128 + k)*128 + n], t) : (uint16_t)0;
    }
}

// ---------------------------------------------------------------------------
// k1 (HMMA bf16 3-term, R8-proven): grid (128, 2)
// ---------------------------------------------------------------------------
#define OFF1_W  0
#define OFF1_A  139264
#define OFF1_B1 208896
#define SMEM1   209920

__global__ __launch_bounds__(256, 1)
void k1_hmma(const float* __restrict__ feats, const float* __restrict__ b1)
{
    extern __shared__ char sm1[];
    uint16_t* sW   = (uint16_t*)(sm1 + OFF1_W);
    uint16_t* sAhi = (uint16_t*)(sm1 + OFF1_A);
    uint16_t* sAlo = sAhi + 128*136;
    float*    sb1  = (float*)(sm1 + OFF1_B1);
    uint32_t  swb  = smem_u32(sm1);

    int tid = threadIdx.x, lane = tid & 31, wid = tid >> 5;
    int wm = wid >> 2, wn = wid & 3, g4 = lane >> 2, l4 = lane & 3;
    int m0 = blockIdx.x * 128, hf = blockIdx.y;

    {
        const char* src = (const char*)(g_W1p + hf*69632) + tid*16;
        uint32_t dst = swb + OFF1_W + tid*16;
        #pragma unroll
        for (int it = 0; it < 34; ++it) cp16(dst + it*4096, src + it*4096);
        asm volatile("cp.async.commit_group;" ::: "memory");
    }
    sb1[tid] = (hf == 0) ? b1[tid] : 0.f;

    {
        int r = tid >> 1, kb = (tid & 1) * 64;
        const float* fr = feats + (size_t)(m0 + r)*CIN + kb;
        uint16_t* ph = sAhi + r*136 + kb;
        uint16_t* pl = sAlo + r*136 + kb;
        #pragma unroll
        for (int j = 0; j < 16; ++j) {
            float4 v = *(const float4*)(fr + 4*j);
            uint32_t h01, l01, h23, l23;
            split2(v.x, v.y, h01, l01);
            split2(v.z, v.w, h23, l23);
            *(uint32_t*)(ph + 4*j)     = h01;
            *(uint32_t*)(ph + 4*j + 2) = h23;
            *(uint32_t*)(pl + 4*j)     = l01;
            *(uint32_t*)(pl + 4*j + 2) = l23;
        }
    }
    asm volatile("cp.async.wait_group 0;" ::: "memory");
    __syncthreads();

    float acc[4][8][4];
    #pragma unroll
    for (int mi = 0; mi < 4; ++mi)
        #pragma unroll
        for (int ni = 0; ni < 8; ++ni)
            #pragma unroll
            for (int q = 0; q < 4; ++q) acc[mi][ni][q] = 0.f;

    const uint16_t* sWl = sW + 34816;
    #pragma unroll
    for (int ks = 0; ks < 8; ++ks) {
        int kk = ks*16 + l4*2;
        uint32_t ah[4][4], al[4][4], bb[8][2];
        #pragma unroll
        for (int mi = 0; mi < 4; ++mi) {
            const uint16_t* pa = sAhi + (wm*64 + mi*16 + g4)*136 + kk;
            ah[mi][0] = *(const uint32_t*)pa;
            ah[mi][1] = *(const uint32_t*)(pa + 8*136);
            ah[mi][2] = *(const uint32_t*)(pa + 8);
            ah[mi][3] = *(const uint32_t*)(pa + 8*136 + 8);
            const uint16_t* pb = sAlo + (wm*64 + mi*16 + g4)*136 + kk;
            al[mi][0] = *(const uint32_t*)pb;
            al[mi][1] = *(const uint32_t*)(pb + 8*136);
            al[mi][2] = *(const uint32_t*)(pb + 8);
            al[mi][3] = *(const uint32_t*)(pb + 8*136 + 8);
        }
        #pragma unroll
        for (int ni = 0; ni < 8; ++ni) {
            const uint16_t* p = sW + (wn*64 + ni*8 + g4)*136 + kk;
            bb[ni][0] = *(const uint32_t*)p;
            bb[ni][1] = *(const uint32_t*)(p + 8);
        }
        #pragma unroll
        for (int mi = 0; mi < 4; ++mi)
            #pragma unroll
            for (int ni = 0; ni < 8; ++ni) {
                mma_bf16(acc[mi][ni], ah[mi], bb[ni]);
                mma_bf16(acc[mi][ni], al[mi], bb[ni]);
            }
        #pragma unroll
        for (int ni = 0; ni < 8; ++ni) {
            const uint16_t* q = sWl + (wn*64 + ni*8 + g4)*136 + kk;
            bb[ni][0] = *(const uint32_t*)q;
            bb[ni][1] = *(const uint32_t*)(q + 8);
        }
        #pragma unroll
        for (int mi = 0; mi < 4; ++mi)
            #pragma unroll
            for (int ni = 0; ni < 8; ++ni)
                mma_bf16(acc[mi][ni], ah[mi], bb[ni]);
    }

    float* Out = hf ? g_Bm : g_A;
    #pragma unroll
    for (int mi = 0; mi < 4; ++mi) {
        int m = wm*64 + mi*16 + g4;
        #pragma unroll
        for (int ni = 0; ni < 8; ++ni) {
            int n0 = wn*64 + ni*8 + l4*2;
            float b0 = sb1[n0], bv1 = sb1[n0 + 1];
            *(float2*)(Out + (size_t)(m0 + m)*H + n0) =
                make_float2(acc[mi][ni][0] + b0, acc[mi][ni][1] + bv1);
            *(float2*)(Out + (size_t)(m0 + m + 8)*H + n0) =
                make_float2(acc[mi][ni][2] + b0, acc[mi][ni][3] + bv1);
        }
    }
}

// ---------------------------------------------------------------------------
// k2: edge MLP layer-2, fp16 single-term HMMA, coalesced warp-per-node gather.
// __launch_bounds__(256,1): accumulators MUST stay in registers (no 128-reg cap).
// ---------------------------------------------------------------------------
#define OFF_H1   0          // fp16 [128][264] = 67584
#define OFF_W2s  67584      // 2 stages x fp16[256][40] = 2 x 20480
#define OFF_B2   108544     // 256 floats
#define OFF_SIDX 109568
#define OFF_SVAL 110080
#define SMEM2    110592

__global__ __launch_bounds__(256, 1)
void k2_edge(const int* __restrict__ n_idxs, const int* __restrict__ nvalid,
             const float* __restrict__ b2)
{
    extern __shared__ char smem[];
    uint16_t* sh1  = (uint16_t*)(smem + OFF_H1);      // fp16 [128][264]
    float*    sb2  = (float*)(smem + OFF_B2);
    int*      sidx = (int*)(smem + OFF_SIDX);
    float*    sval = (float*)(smem + OFF_SVAL);
    uint32_t  swbase = smem_u32(smem) + OFF_W2s;

    int tid = threadIdx.x, lane = tid & 31, wid = tid >> 5;
    int wm = wid >> 2, wn = wid & 3;
    int node0 = blockIdx.x * 8;

    // prologue: stream W2 chunks 0,1 (20480B each = 5 x 16B/thread)
    #pragma unroll
    for (int s = 0; s < 2; ++s) {
        const char* src = (const char*)g_W2h + s*20480 + tid*16;
        uint32_t dst = swbase + s*20480 + tid*16;
        #pragma unroll
        for (int it = 0; it < 5; ++it)
            cp16(dst + it*4096, src + it*4096);
        asm volatile("cp.async.commit_group;" ::: "memory");
    }

    if (tid < 128) {
        sidx[tid] = n_idxs[node0*K_ + tid];
        sval[tid] = nvalid[node0*K_ + tid] ? 1.f : 0.f;
    }
    sb2[tid] = b2[tid];
    __syncthreads();

    // build h1 (fp16): warp w owns node node0+w; 16 edges, fully coalesced.
    {
        int node = node0 + wid;
        int boff = (node >> 12) * N_;
        const float* arow = g_A + (size_t)node * H;
        float4 a0 = *(const float4*)(arow + 4*lane);
        float4 a1 = *(const float4*)(arow + 128 + 4*lane);
        #pragma unroll 4
        for (int i = 0; i < 16; ++i) {
            int e = wid*16 + i;
            const float* brow = g_Bm + (size_t)(boff + sidx[e]) * H;
            float4 v0 = *(const float4*)(brow + 4*lane);
            float4 v1 = *(const float4*)(brow + 128 + 4*lane);
            uint2 w0, w1;
            w0.x = pack_h2(fmaxf(a0.x + v0.x, 0.f), fmaxf(a0.y + v0.y, 0.f));
            w0.y = pack_h2(fmaxf(a0.z + v0.z, 0.f), fmaxf(a0.w + v0.w, 0.f));
            w1.x = pack_h2(fmaxf(a1.x + v1.x, 0.f), fmaxf(a1.y + v1.y, 0.f));
            w1.y = pack_h2(fmaxf(a1.z + v1.z, 0.f), fmaxf(a1.w + v1.w, 0.f));
            uint16_t* ph = sh1 + e*264;
            *(uint2*)(ph + 4*lane)       = w0;
            *(uint2*)(ph + 128 + 4*lane) = w1;
        }
    }

    float acc[4][8][4];
    #pragma unroll
    for (int mi = 0; mi < 4; ++mi)
        #pragma unroll
        for (int ni = 0; ni < 8; ++ni)
            #pragma unroll
            for (int q = 0; q < 4; ++q) acc[mi][ni][q] = 0.f;

    int g4 = lane >> 2, l4 = lane & 3;

    for (int c = 0; c < 8; ++c) {
        if (c == 7) asm volatile("cp.async.wait_group 0;" ::: "memory");
        else        asm volatile("cp.async.wait_group 1;" ::: "memory");
        __syncthreads();

        const uint16_t* sWc = (const uint16_t*)(smem + OFF_W2s + (c & 1)*20480);

        #pragma unroll
        for (int ks = 0; ks < 2; ++ks) {
            int kk = c*32 + ks*16 + l4*2;
            uint32_t ah[4][4], bb[8][2];
            #pragma unroll
            for (int mi = 0; mi < 4; ++mi) {
                const uint16_t* pa = sh1 + (wm*64 + mi*16 + g4)*264 + kk;
                ah[mi][0] = *(const uint32_t*)pa;
                ah[mi][1] = *(const uint32_t*)(pa + 8*264);
                ah[mi][2] = *(const uint32_t*)(pa + 8);
                ah[mi][3] = *(const uint32_t*)(pa + 8*264 + 8);
            }
            #pragma unroll
            for (int ni = 0; ni < 8; ++ni) {
                const uint16_t* p = sWc + (wn*64 + ni*8 + g4)*40 + ks*16 + l4*2;
                bb[ni][0] = *(const uint32_t*)p;
                bb[ni][1] = *(const uint32_t*)(p + 8);
            }
            #pragma unroll
            for (int mi = 0; mi < 4; ++mi)
                #pragma unroll
                for (int ni = 0; ni < 8; ++ni)
                    mma_f16(acc[mi][ni], ah[mi], bb[ni]);
        }
        __syncthreads();
        if (c < 6) {
            const char* src = (const char*)g_W2h + (c + 2)*20480 + tid*16;
            uint32_t dst = swbase + (c & 1)*20480 + tid*16;
            #pragma unroll
            for (int it = 0; it < 5; ++it)
                cp16(dst + it*4096, src + it*4096);
            asm volatile("cp.async.commit_group;" ::: "memory");
        }
    }

    // epilogue: bias + relu + mask, butterfly over 16 edges, store g_S
    #pragma unroll
    for (int mi = 0; mi < 4; ++mi) {
        int node_l = wm*4 + mi;
        float m1 = sval[node_l*16 + g4];
        float m2 = sval[node_l*16 + g4 + 8];
        int node_g = node0 + node_l;
        #pragma unroll
        for (int ni = 0; ni < 8; ++ni) {
            int n0 = wn*64 + ni*8 + l4*2;
            float s0 = fmaxf(acc[mi][ni][0] + sb2[n0],     0.f)*m1
                     + fmaxf(acc[mi][ni][2] + sb2[n0],     0.f)*m2;
            float s1 = fmaxf(acc[mi][ni][1] + sb2[n0 + 1], 0.f)*m1
                     + fmaxf(acc[mi][ni][3] + sb2[n0 + 1], 0.f)*m2;
            #pragma unroll
            for (int d = 4; d < 32; d <<= 1) {
                s0 += __shfl_xor_sync(0xFFFFFFFF, s0, d);
                s1 += __shfl_xor_sync(0xFFFFFFFF, s1, d);
            }
            if (g4 == 0)
                *(float2*)(g_S + (size_t)node_g*H + n0) = make_float2(s0, s1);
        }
    }
}

// ---------------------------------------------------------------------------
// k3 (HMMA bf16 3-term, R7-proven): grid 128
// ---------------------------------------------------------------------------
#define OFF3_A   0
#define OFF3_W   135168
#define OFF3_B3  204800
#define OFF3_CNT 205312
#define SMEM3    205824

__global__ __launch_bounds__(256, 1)
void k3_hmma(const int* __restrict__ nvalid, const float* __restrict__ b3,
             float* __restrict__ out)
{
    extern __shared__ char sm3[];
    uint16_t* sAhi = (uint16_t*)(sm3 + OFF3_A);
    uint16_t* sAlo = sAhi + 128*264;
    float*    sb3  = (float*)(sm3 + OFF3_B3);
    float*    scnt = (float*)(sm3 + OFF3_CNT);
    uint32_t  swb  = smem_u32(sm3);

    int tid = threadIdx.x, lane = tid & 31, wid = tid >> 5;
    int wm = wid >> 2, wn = wid & 3, g4 = lane >> 2, l4 = lane & 3;
    int m0 = blockIdx.x * 128;

    {
        const char* src = (const char*)g_W3p + tid*16;
        uint32_t dst = swb + OFF3_W + tid*16;
        #pragma unroll
        for (int it = 0; it < 17; ++it) cp16(dst + it*4096, src + it*4096);
        asm volatile("cp.async.commit_group;" ::: "memory");
    }
    if (tid < 128) {
        sb3[tid] = b3[tid];
        int c = 0;
        #pragma unroll
        for (int k = 0; k < K_; ++k) c += nvalid[(m0 + tid)*K_ + k];
        scnt[tid] = (float)c;
    }

    {
        int r = tid >> 1, kb = (tid & 1) * 128;
        const float* fr = g_S + (size_t)(m0 + r)*H + kb;
        uint16_t* ph = sAhi + r*264 + kb;
        uint16_t* pl = sAlo + r*264 + kb;
        #pragma unroll
        for (int j = 0; j < 32; ++j) {
            float4 v = *(const float4*)(fr + 4*j);
            uint32_t h01, l01, h23, l23;
            split2(v.x, v.y, h01, l01);
            split2(v.z, v.w, h23, l23);
            *(uint32_t*)(ph + 4*j)     = h01;
            *(uint32_t*)(ph + 4*j + 2) = h23;
            *(uint32_t*)(pl + 4*j)     = l01;
            *(uint32_t*)(pl + 4*j + 2) = l23;
        }
    }
    asm volatile("cp.async.wait_group 0;" ::: "memory");
    __syncthreads();

    float acc[4][4][4];
    #pragma unroll
    for (int mi = 0; mi < 4; ++mi)
        #pragma unroll
        for (int ni = 0; ni < 4; ++ni)
            #pragma unroll
            for (int q = 0; q < 4; ++q) acc[mi][ni][q] = 0.f;

    for (int kc = 0; kc < 2; ++kc) {
        const uint16_t* sW  = (const uint16_t*)(sm3 + OFF3_W);
        const uint16_t* sWl = sW + 17408;

        #pragma unroll
        for (int ks = 0; ks < 8; ++ks) {
            int kk = ks*16 + l4*2;
            int ka = kc*128 + kk;
            uint32_t ah[4][4], al[4][4], bb[4][2];
            #pragma unroll
            for (int mi = 0; mi < 4; ++mi) {
                const uint16_t* pa = sAhi + (wm*64 + mi*16 + g4)*264 + ka;
                ah[mi][0] = *(const uint32_t*)pa;
                ah[mi][1] = *(const uint32_t*)(pa + 8*264);
                ah[mi][2] = *(const uint32_t*)(pa + 8);
                ah[mi][3] = *(const uint32_t*)(pa + 8*264 + 8);
                const uint16_t* pb = sAlo + (wm*64 + mi*16 + g4)*264 + ka;
                al[mi][0] = *(const uint32_t*)pb;
                al[mi][1] = *(const uint32_t*)(pb + 8*264);
                al[mi][2] = *(const uint32_t*)(pb + 8);
                al[mi][3] = *(const uint32_t*)(pb + 8*264 + 8);
            }
            #pragma unroll
            for (int ni = 0; ni < 4; ++ni) {
                const uint16_t* p = sW + (wn*32 + ni*8 + g4)*136 + kk;
                bb[ni][0] = *(const uint32_t*)p;
                bb[ni][1] = *(const uint32_t*)(p + 8);
            }
            #pragma unroll
            for (int mi = 0; mi < 4; ++mi)
                #pragma unroll
                for (int ni = 0; ni < 4; ++ni) {
                    mma_bf16(acc[mi][ni], ah[mi], bb[ni]);
                    mma_bf16(acc[mi][ni], al[mi], bb[ni]);
                }
            #pragma unroll
            for (int ni = 0; ni < 4; ++ni) {
                const uint16_t* q = sWl + (wn*32 + ni*8 + g4)*136 + kk;
                bb[ni][0] = *(const uint32_t*)q;
                bb[ni][1] = *(const uint32_t*)(q + 8);
            }
            #pragma unroll
            for (int mi = 0; mi < 4; ++mi)
                #pragma unroll
                for (int ni = 0; ni < 4; ++ni)
                    mma_bf16(acc[mi][ni], ah[mi], bb[ni]);
        }
        __syncthreads();
        if (kc == 0) {
            const char* src = (const char*)g_W3p + 69632 + tid*16;
            uint32_t dst = swb + OFF3_W + tid*16;
            #pragma unroll
            for (int it = 0; it < 17; ++it) cp16(dst + it*4096, src + it*4096);
            asm volatile("cp.async.commit_group;" ::: "memory");
            asm volatile("cp.async.wait_group 0;" ::: "memory");
            __syncthreads();
        }
    }

    #pragma unroll
    for (int mi = 0; mi < 4; ++mi) {
        int m = wm*64 + mi*16 + g4;
        #pragma unroll
        for (int ni = 0; ni < 4; ++ni) {
            int n0 = wn*32 + ni*8 + l4*2;
            float b0 = sb3[n0], bv1 = sb3[n0 + 1];
            *(float2*)(out + (size_t)(m0 + m)*COUT + n0) =
                make_float2(acc[mi][ni][0] + b0*scnt[m], acc[mi][ni][1] + bv1*scnt[m]);
            *(float2*)(out + (size_t)(m0 + m + 8)*COUT + n0) =
                make_float2(acc[mi][ni][2] + b0*scnt[m + 8], acc[mi][ni][3] + bv1*scnt[m + 8]);
        }
    }
}

// ---------------------------------------------------------------------------
extern "C" void kernel_launch(void* const* d_in, const int* in_sizes, int n_in,
                              void* d_out, int out_size)
{
    const float* feats  = (const float*)d_in[2];
    const int*   n_idxs = (const int*)  d_in[3];
    const int*   nvalid = (const int*)  d_in[4];
    const float* W1     = (const float*)d_in[5];
    const float* b1     = (const float*)d_in[6];
    const float* W2     = (const float*)d_in[7];
    const float* b2     = (const float*)d_in[8];
    const float* W3     = (const float*)d_in[9];
    const float* b3     = (const float*)d_in[10];
    float* out = (float*)d_out;

    cudaFuncSetAttribute(k1_hmma, cudaFuncAttributeMaxDynamicSharedMemorySize, SMEM1);
    cudaFuncSetAttribute(k2_edge, cudaFuncAttributeMaxDynamicSharedMemorySize, SMEM2);
    cudaFuncSetAttribute(k3_hmma, cudaFuncAttributeMaxDynamicSharedMemorySize, SMEM3);

    k0_prep<<<1136, 256>>>(W1, W2, W3);
    k1_hmma<<<dim3(128, 2), 256, SMEM1>>>(feats, b1);
    k2_edge<<<NODES/8, 256, SMEM2>>>(n_idxs, nvalid, b2);
    k3_hmma<<<128, 256, SMEM3>>>(nvalid, b3, out);
}

// round 12
// speedup vs baseline: 4.8561x; 1.0704x over previous
#include <cuda_runtime.h>
#include <cuda_bf16.h>
#include <cuda_fp16.h>
#include <cstdint>

#define B_    4
#define N_    4096
#define K_    16
#define CIN   128
#define H     256
#define COUT  128
#define NODES (B_*N_)

__device__ __align__(16) uint16_t g_Ah[NODES*H];  // fp16: feats@W1[:128,:] + b1
__device__ __align__(16) uint16_t g_Bh[NODES*H];  // fp16: feats@W1[128:,:]
__device__ float g_S [NODES*H];                   // fp32: sum_k mask*h2
// W1 packed fp16 (single term): [hf:2][n:256][k:136]
__device__ __align__(16) uint16_t g_W1h[2*256*136];
// W2 packed fp16 (single term): [chunk c:8][n:256][k:40]
__device__ __align__(16) uint16_t g_W2h[8*256*40];
// W3 split/packed bf16: [kc:2][t:2][n:128][k:136]
__device__ __align__(16) uint16_t g_W3p[2*2*128*136];

// ---------------- helpers ----------------
__device__ __forceinline__ uint32_t smem_u32(const void* p) {
    uint32_t a;
    asm("{ .reg .u64 t; cvta.to.shared.u64 t, %1; cvt.u32.u64 %0, t; }" : "=r"(a) : "l"(p));
    return a;
}
__device__ __forceinline__ void mma_bf16(float* d, const uint32_t* a, const uint32_t* b) {
    asm volatile("mma.sync.aligned.m16n8k16.row.col.f32.bf16.bf16.f32 "
        "{%0,%1,%2,%3}, {%4,%5,%6,%7}, {%8,%9}, {%0,%1,%2,%3};"
        : "+f"(d[0]), "+f"(d[1]), "+f"(d[2]), "+f"(d[3])
        : "r"(a[0]), "r"(a[1]), "r"(a[2]), "r"(a[3]), "r"(b[0]), "r"(b[1]));
}
__device__ __forceinline__ void mma_f16(float* d, const uint32_t* a, const uint32_t* b) {
    asm volatile("mma.sync.aligned.m16n8k16.row.col.f32.f16.f16.f32 "
        "{%0,%1,%2,%3}, {%4,%5,%6,%7}, {%8,%9}, {%0,%1,%2,%3};"
        : "+f"(d[0]), "+f"(d[1]), "+f"(d[2]), "+f"(d[3])
        : "r"(a[0]), "r"(a[1]), "r"(a[2]), "r"(a[3]), "r"(b[0]), "r"(b[1]));
}
__device__ __forceinline__ void cp16(uint32_t sdst, const void* gsrc) {
    asm volatile("cp.async.cg.shared.global [%0], [%1], 16;" :: "r"(sdst), "l"(gsrc));
}
__device__ __forceinline__ void split2(float x, float y, uint32_t& hi, uint32_t& lo) {
    __nv_bfloat16 hx = __float2bfloat16(x), hy = __float2bfloat16(y);
    __nv_bfloat16 lx = __float2bfloat16(x - __bfloat162float(hx));
    __nv_bfloat16 ly = __float2bfloat16(y - __bfloat162float(hy));
    __nv_bfloat162 hp(hx, hy), lp(lx, ly);
    hi = *reinterpret_cast<uint32_t*>(&hp);
    lo = *reinterpret_cast<uint32_t*>(&lp);
}
__device__ __forceinline__ uint16_t split_pick(float w, int t) {
    __nv_bfloat16 hi = __float2bfloat16(w);
    if (t == 0) return *reinterpret_cast<uint16_t*>(&hi);
    __nv_bfloat16 lo = __float2bfloat16(w - __bfloat162float(hi));
    return *reinterpret_cast<uint16_t*>(&lo);
}
__device__ __forceinline__ uint32_t pack_h2(float x, float y) {
    __half2 p = __floats2half2_rn(x, y);
    return *reinterpret_cast<uint32_t*>(&p);
}
__device__ __forceinline__ uint32_t relu_add_h2(uint32_t a, uint32_t b) {
    __half2 ha = *reinterpret_cast<__half2*>(&a);
    __half2 hb = *reinterpret_cast<__half2*>(&b);
    __half2 z  = __floats2half2_rn(0.f, 0.f);
    __half2 r  = __hmax2(__hadd2(ha, hb), z);
    return *reinterpret_cast<uint32_t*>(&r);
}

// ---------------------------------------------------------------------------
// k0: pack W1 (fp16), W2 (fp16), W3 (bf16 hi/lo). Bounds-clean.
// ---------------------------------------------------------------------------
__global__ void k0_prep(const float* __restrict__ W1, const float* __restrict__ W2,
                        const float* __restrict__ W3)
{
    int i = blockIdx.x * 256 + threadIdx.x;
    if (i < 81920) {                                   // W2: [c][n][40] fp16
        int kl = i % 40, n = (i / 40) % 256, c = i / 10240;
        __half v = (kl < 32) ? __float2half_rn(W2[(c*32 + kl)*256 + n]) : __half(0.f);
        g_W2h[i] = *reinterpret_cast<uint16_t*>(&v);
    } else if (i < 81920 + 69632) {                    // W1: [hf][n][136] fp16
        int j = i - 81920;
        int k = j % 136, n = (j / 136) % 256, hf = j / 34816;
        __half v = (k < 128) ? __float2half_rn(W1[(hf*128 + k)*256 + n]) : __half(0.f);
        g_W1h[j] = *reinterpret_cast<uint16_t*>(&v);
    } else if (i < 81920 + 69632 + 69632) {            // W3: [kc][t][n][136] bf16
        int j = i - 151552;
        int k = j % 136, n = (j / 136) % 128, t = (j / 17408) % 2, kc = j / 34816;
        g_W3p[j] = (k < 128) ? split_pick(W3[(kc*128 + k)*128 + n], t) : (uint16_t)0;
    }
}

// ---------------------------------------------------------------------------
// k1 (HMMA fp16 single-term): [16384x128]@[128x256] -> g_Ah(+b1) | g_Bh
// grid (128, 2)
// ---------------------------------------------------------------------------
#define OFF1_W  0          // fp16 [256][136] = 69632 B
#define OFF1_A  69632      // fp16 [128][136] = 34816 B
#define OFF1_B1 104448     // 256 floats
#define SMEM1   105472

__global__ __launch_bounds__(256, 1)
void k1_hmma(const float* __restrict__ feats, const float* __restrict__ b1)
{
    extern __shared__ char sm1[];
    uint16_t* sW  = (uint16_t*)(sm1 + OFF1_W);
    uint16_t* sA  = (uint16_t*)(sm1 + OFF1_A);
    float*    sb1 = (float*)(sm1 + OFF1_B1);
    uint32_t  swb = smem_u32(sm1);

    int tid = threadIdx.x, lane = tid & 31, wid = tid >> 5;
    int wm = wid >> 2, wn = wid & 3, g4 = lane >> 2, l4 = lane & 3;
    int m0 = blockIdx.x * 128, hf = blockIdx.y;

    // stream W half (fp16): 69632 B = 17 x 16B/thread
    {
        const char* src = (const char*)(g_W1h + hf*34816) + tid*16;
        uint32_t dst = swb + OFF1_W + tid*16;
        #pragma unroll
        for (int it = 0; it < 17; ++it) cp16(dst + it*4096, src + it*4096);
        asm volatile("cp.async.commit_group;" ::: "memory");
    }
    sb1[tid] = (hf == 0) ? b1[tid] : 0.f;

    // build A (fp16): thread -> row tid/2, k-half (tid&1)*64
    {
        int r = tid >> 1, kb = (tid & 1) * 64;
        const float* fr = feats + (size_t)(m0 + r)*CIN + kb;
        uint16_t* ph = sA + r*136 + kb;
        #pragma unroll
        for (int j = 0; j < 16; ++j) {
            float4 v = *(const float4*)(fr + 4*j);
            *(uint32_t*)(ph + 4*j)     = pack_h2(v.x, v.y);
            *(uint32_t*)(ph + 4*j + 2) = pack_h2(v.z, v.w);
        }
    }
    asm volatile("cp.async.wait_group 0;" ::: "memory");
    __syncthreads();

    float acc[4][8][4];
    #pragma unroll
    for (int mi = 0; mi < 4; ++mi)
        #pragma unroll
        for (int ni = 0; ni < 8; ++ni)
            #pragma unroll
            for (int q = 0; q < 4; ++q) acc[mi][ni][q] = 0.f;

    #pragma unroll
    for (int ks = 0; ks < 8; ++ks) {
        int kk = ks*16 + l4*2;
        uint32_t ah[4][4], bb[8][2];
        #pragma unroll
        for (int mi = 0; mi < 4; ++mi) {
            const uint16_t* pa = sA + (wm*64 + mi*16 + g4)*136 + kk;
            ah[mi][0] = *(const uint32_t*)pa;
            ah[mi][1] = *(const uint32_t*)(pa + 8*136);
            ah[mi][2] = *(const uint32_t*)(pa + 8);
            ah[mi][3] = *(const uint32_t*)(pa + 8*136 + 8);
        }
        #pragma unroll
        for (int ni = 0; ni < 8; ++ni) {
            const uint16_t* p = sW + (wn*64 + ni*8 + g4)*136 + kk;
            bb[ni][0] = *(const uint32_t*)p;
            bb[ni][1] = *(const uint32_t*)(p + 8);
        }
        #pragma unroll
        for (int mi = 0; mi < 4; ++mi)
            #pragma unroll
            for (int ni = 0; ni < 8; ++ni)
                mma_f16(acc[mi][ni], ah[mi], bb[ni]);
    }

    uint16_t* Out = hf ? g_Bh : g_Ah;
    #pragma unroll
    for (int mi = 0; mi < 4; ++mi) {
        int m = wm*64 + mi*16 + g4;
        #pragma unroll
        for (int ni = 0; ni < 8; ++ni) {
            int n0 = wn*64 + ni*8 + l4*2;
            float b0 = sb1[n0], bv1 = sb1[n0 + 1];
            *(uint32_t*)(Out + (size_t)(m0 + m)*H + n0) =
                pack_h2(acc[mi][ni][0] + b0, acc[mi][ni][1] + bv1);
            *(uint32_t*)(Out + (size_t)(m0 + m + 8)*H + n0) =
                pack_h2(acc[mi][ni][2] + b0, acc[mi][ni][3] + bv1);
        }
    }
}

// ---------------------------------------------------------------------------
// k2: edge MLP layer-2, fp16 single-term HMMA, fp16 coalesced gather.
// ---------------------------------------------------------------------------
#define OFF_H1   0          // fp16 [128][264] = 67584
#define OFF_W2s  67584      // 2 stages x fp16[256][40] = 2 x 20480
#define OFF_B2   108544     // 256 floats
#define OFF_SIDX 109568
#define OFF_SVAL 110080
#define SMEM2    110592

__global__ __launch_bounds__(256, 1)
void k2_edge(const int* __restrict__ n_idxs, const int* __restrict__ nvalid,
             const float* __restrict__ b2)
{
    extern __shared__ char smem[];
    uint16_t* sh1  = (uint16_t*)(smem + OFF_H1);      // fp16 [128][264]
    float*    sb2  = (float*)(smem + OFF_B2);
    int*      sidx = (int*)(smem + OFF_SIDX);
    float*    sval = (float*)(smem + OFF_SVAL);
    uint32_t  swbase = smem_u32(smem) + OFF_W2s;

    int tid = threadIdx.x, lane = tid & 31, wid = tid >> 5;
    int wm = wid >> 2, wn = wid & 3;
    int node0 = blockIdx.x * 8;

    // prologue: stream W2 chunks 0,1 (20480B each = 5 x 16B/thread)
    #pragma unroll
    for (int s = 0; s < 2; ++s) {
        const char* src = (const char*)g_W2h + s*20480 + tid*16;
        uint32_t dst = swbase + s*20480 + tid*16;
        #pragma unroll
        for (int it = 0; it < 5; ++it)
            cp16(dst + it*4096, src + it*4096);
        asm volatile("cp.async.commit_group;" ::: "memory");
    }

    if (tid < 128) {
        sidx[tid] = n_idxs[node0*K_ + tid];
        sval[tid] = nvalid[node0*K_ + tid] ? 1.f : 0.f;
    }
    sb2[tid] = b2[tid];
    __syncthreads();

    // build h1 (fp16): warp w owns node node0+w; 16 edges, 1 LDG.128/edge.
    // lane covers cols [8*lane, 8*lane+8).
    {
        int node = node0 + wid;
        int boff = (node >> 12) * N_;
        const uint16_t* arow = g_Ah + (size_t)node * H;
        uint4 a = *(const uint4*)(arow + 8*lane);
        #pragma unroll 4
        for (int i = 0; i < 16; ++i) {
            int e = wid*16 + i;
            const uint16_t* brow = g_Bh + (size_t)(boff + sidx[e]) * H;
            uint4 v = *(const uint4*)(brow + 8*lane);
            uint4 h;
            h.x = relu_add_h2(a.x, v.x);
            h.y = relu_add_h2(a.y, v.y);
            h.z = relu_add_h2(a.z, v.z);
            h.w = relu_add_h2(a.w, v.w);
            *(uint4*)(sh1 + e*264 + 8*lane) = h;
        }
    }

    float acc[4][8][4];
    #pragma unroll
    for (int mi = 0; mi < 4; ++mi)
        #pragma unroll
        for (int ni = 0; ni < 8; ++ni)
            #pragma unroll
            for (int q = 0; q < 4; ++q) acc[mi][ni][q] = 0.f;

    int g4 = lane >> 2, l4 = lane & 3;

    for (int c = 0; c < 8; ++c) {
        if (c == 7) asm volatile("cp.async.wait_group 0;" ::: "memory");
        else        asm volatile("cp.async.wait_group 1;" ::: "memory");
        __syncthreads();

        const uint16_t* sWc = (const uint16_t*)(smem + OFF_W2s + (c & 1)*20480);

        #pragma unroll
        for (int ks = 0; ks < 2; ++ks) {
            int kk = c*32 + ks*16 + l4*2;
            uint32_t ah[4][4], bb[8][2];
            #pragma unroll
            for (int mi = 0; mi < 4; ++mi) {
                const uint16_t* pa = sh1 + (wm*64 + mi*16 + g4)*264 + kk;
                ah[mi][0] = *(const uint32_t*)pa;
                ah[mi][1] = *(const uint32_t*)(pa + 8*264);
                ah[mi][2] = *(const uint32_t*)(pa + 8);
                ah[mi][3] = *(const uint32_t*)(pa + 8*264 + 8);
            }
            #pragma unroll
            for (int ni = 0; ni < 8; ++ni) {
                const uint16_t* p = sWc + (wn*64 + ni*8 + g4)*40 + ks*16 + l4*2;
                bb[ni][0] = *(const uint32_t*)p;
                bb[ni][1] = *(const uint32_t*)(p + 8);
            }
            #pragma unroll
            for (int mi = 0; mi < 4; ++mi)
                #pragma unroll
                for (int ni = 0; ni < 8; ++ni)
                    mma_f16(acc[mi][ni], ah[mi], bb[ni]);
        }
        __syncthreads();
        if (c < 6) {
            const char* src = (const char*)g_W2h + (c + 2)*20480 + tid*16;
            uint32_t dst = swbase + (c & 1)*20480 + tid*16;
            #pragma unroll
            for (int it = 0; it < 5; ++it)
                cp16(dst + it*4096, src + it*4096);
            asm volatile("cp.async.commit_group;" ::: "memory");
        }
    }

    // epilogue: bias + relu + mask, butterfly over 16 edges, store g_S
    #pragma unroll
    for (int mi = 0; mi < 4; ++mi) {
        int node_l = wm*4 + mi;
        float m1 = sval[node_l*16 + g4];
        float m2 = sval[node_l*16 + g4 + 8];
        int node_g = node0 + node_l;
        #pragma unroll
        for (int ni = 0; ni < 8; ++ni) {
            int n0 = wn*64 + ni*8 + l4*2;
            float s0 = fmaxf(acc[mi][ni][0] + sb2[n0],     0.f)*m1
                     + fmaxf(acc[mi][ni][2] + sb2[n0],     0.f)*m2;
            float s1 = fmaxf(acc[mi][ni][1] + sb2[n0 + 1], 0.f)*m1
                     + fmaxf(acc[mi][ni][3] + sb2[n0 + 1], 0.f)*m2;
            #pragma unroll
            for (int d = 4; d < 32; d <<= 1) {
                s0 += __shfl_xor_sync(0xFFFFFFFF, s0, d);
                s1 += __shfl_xor_sync(0xFFFFFFFF, s1, d);
            }
            if (g4 == 0)
                *(float2*)(g_S + (size_t)node_g*H + n0) = make_float2(s0, s1);
        }
    }
}

// ---------------------------------------------------------------------------
// k3 (HMMA bf16 3-term, R7-proven): grid 128
// ---------------------------------------------------------------------------
#define OFF3_A   0
#define OFF3_W   135168
#define OFF3_B3  204800
#define OFF3_CNT 205312
#define SMEM3    205824

__global__ __launch_bounds__(256, 1)
void k3_hmma(const int* __restrict__ nvalid, const float* __restrict__ b3,
             float* __restrict__ out)
{
    extern __shared__ char sm3[];
    uint16_t* sAhi = (uint16_t*)(sm3 + OFF3_A);
    uint16_t* sAlo = sAhi + 128*264;
    float*    sb3  = (float*)(sm3 + OFF3_B3);
    float*    scnt = (float*)(sm3 + OFF3_CNT);
    uint32_t  swb  = smem_u32(sm3);

    int tid = threadIdx.x, lane = tid & 31, wid = tid >> 5;
    int wm = wid >> 2, wn = wid & 3, g4 = lane >> 2, l4 = lane & 3;
    int m0 = blockIdx.x * 128;

    {
        const char* src = (const char*)g_W3p + tid*16;
        uint32_t dst = swb + OFF3_W + tid*16;
        #pragma unroll
        for (int it = 0; it < 17; ++it) cp16(dst + it*4096, src + it*4096);
        asm volatile("cp.async.commit_group;" ::: "memory");
    }
    if (tid < 128) {
        sb3[tid] = b3[tid];
        int c = 0;
        #pragma unroll
        for (int k = 0; k < K_; ++k) c += nvalid[(m0 + tid)*K_ + k];
        scnt[tid] = (float)c;
    }

    {
        int r = tid >> 1, kb = (tid & 1) * 128;
        const float* fr = g_S + (size_t)(m0 + r)*H + kb;
        uint16_t* ph = sAhi + r*264 + kb;
        uint16_t* pl = sAlo + r*264 + kb;
        #pragma unroll
        for (int j = 0; j < 32; ++j) {
            float4 v = *(const float4*)(fr + 4*j);
            uint32_t h01, l01, h23, l23;
            split2(v.x, v.y, h01, l01);
            split2(v.z, v.w, h23, l23);
            *(uint32_t*)(ph + 4*j)     = h01;
            *(uint32_t*)(ph + 4*j + 2) = h23;
            *(uint32_t*)(pl + 4*j)     = l01;
            *(uint32_t*)(pl + 4*j + 2) = l23;
        }
    }
    asm volatile("cp.async.wait_group 0;" ::: "memory");
    __syncthreads();

    float acc[4][4][4];
    #pragma unroll
    for (int mi = 0; mi < 4; ++mi)
        #pragma unroll
        for (int ni = 0; ni < 4; ++ni)
            #pragma unroll
            for (int q = 0; q < 4; ++q) acc[mi][ni][q] = 0.f;

    for (int kc = 0; kc < 2; ++kc) {
        const uint16_t* sW  = (const uint16_t*)(sm3 + OFF3_W);
        const uint16_t* sWl = sW + 17408;

        #pragma unroll
        for (int ks = 0; ks < 8; ++ks) {
            int kk = ks*16 + l4*2;
            int ka = kc*128 + kk;
            uint32_t ah[4][4], al[4][4], bb[4][2];
            #pragma unroll
            for (int mi = 0; mi < 4; ++mi) {
                const uint16_t* pa = sAhi + (wm*64 + mi*16 + g4)*264 + ka;
                ah[mi][0] = *(const uint32_t*)pa;
                ah[mi][1] = *(const uint32_t*)(pa + 8*264);
                ah[mi][2] = *(const uint32_t*)(pa + 8);
                ah[mi][3] = *(const uint32_t*)(pa + 8*264 + 8);
                const uint16_t* pb = sAlo + (wm*64 + mi*16 + g4)*264 + ka;
                al[mi][0] = *(const uint32_t*)pb;
                al[mi][1] = *(const uint32_t*)(pb + 8*264);
                al[mi][2] = *(const uint32_t*)(pb + 8);
                al[mi][3] = *(const uint32_t*)(pb + 8*264 + 8);
            }
            #pragma unroll
            for (int ni = 0; ni < 4; ++ni) {
                const uint16_t* p = sW + (wn*32 + ni*8 + g4)*136 + kk;
                bb[ni][0] = *(const uint32_t*)p;
                bb[ni][1] = *(const uint32_t*)(p + 8);
            }
            #pragma unroll
            for (int mi = 0; mi < 4; ++mi)
                #pragma unroll
                for (int ni = 0; ni < 4; ++ni) {
                    mma_bf16(acc[mi][ni], ah[mi], bb[ni]);
                    mma_bf16(acc[mi][ni], al[mi], bb[ni]);
                }
            #pragma unroll
            for (int ni = 0; ni < 4; ++ni) {
                const uint16_t* q = sWl + (wn*32 + ni*8 + g4)*136 + kk;
                bb[ni][0] = *(const uint32_t*)q;
                bb[ni][1] = *(const uint32_t*)(q + 8);
            }
            #pragma unroll
            for (int mi = 0; mi < 4; ++mi)
                #pragma unroll
                for (int ni = 0; ni < 4; ++ni)
                    mma_bf16(acc[mi][ni], ah[mi], bb[ni]);
        }
        __syncthreads();
        if (kc == 0) {
            const char* src = (const char*)g_W3p + 69632 + tid*16;
            uint32_t dst = swb + OFF3_W + tid*16;
            #pragma unroll
            for (int it = 0; it < 17; ++it) cp16(dst + it*4096, src + it*4096);
            asm volatile("cp.async.commit_group;" ::: "memory");
            asm volatile("cp.async.wait_group 0;" ::: "memory");
            __syncthreads();
        }
    }

    #pragma unroll
    for (int mi = 0; mi < 4; ++mi) {
        int m = wm*64 + mi*16 + g4;
        #pragma unroll
        for (int ni = 0; ni < 4; ++ni) {
            int n0 = wn*32 + ni*8 + l4*2;
            float b0 = sb3[n0], bv1 = sb3[n0 + 1];
            *(float2*)(out + (size_t)(m0 + m)*COUT + n0) =
                make_float2(acc[mi][ni][0] + b0*scnt[m], acc[mi][ni][1] + bv1*scnt[m]);
            *(float2*)(out + (size_t)(m0 + m + 8)*COUT + n0) =
                make_float2(acc[mi][ni][2] + b0*scnt[m + 8], acc[mi][ni][3] + bv1*scnt[m + 8]);
        }
    }
}

// ---------------------------------------------------------------------------
extern "C" void kernel_launch(void* const* d_in, const int* in_sizes, int n_in,
                              void* d_out, int out_size)
{
    const float* feats  = (const float*)d_in[2];
    const int*   n_idxs = (const int*)  d_in[3];
    const int*   nvalid = (const int*)  d_in[4];
    const float* W1     = (const float*)d_in[5];
    const float* b1     = (const float*)d_in[6];
    const float* W2     = (const float*)d_in[7];
    const float* b2     = (const float*)d_in[8];
    const float* W3     = (const float*)d_in[9];
    const float* b3     = (const float*)d_in[10];
    float* out = (float*)d_out;

    cudaFuncSetAttribute(k1_hmma, cudaFuncAttributeMaxDynamicSharedMemorySize, SMEM1);
    cudaFuncSetAttribute(k2_edge, cudaFuncAttributeMaxDynamicSharedMemorySize, SMEM2);
    cudaFuncSetAttribute(k3_hmma, cudaFuncAttributeMaxDynamicSharedMemorySize, SMEM3);

    k0_prep<<<864, 256>>>(W1, W2, W3);
    k1_hmma<<<dim3(128, 2), 256, SMEM1>>>(feats, b1);
    k2_edge<<<NODES/8, 256, SMEM2>>>(n_idxs, nvalid, b2);
    k3_hmma<<<128, 256, SMEM3>>>(nvalid, b3, out);
}